// round 1
// baseline (speedup 1.0000x reference)
#include <cuda_runtime.h>
#include <cuda_bf16.h>
#include <cstddef>

#define BB   1024
#define TT   32
#define VV   1024
#define EE   512
#define HH   1024
#define OO   1024

__device__ float g_wfused[HH * VV];
__device__ float g_bfused[HH];
__device__ float g_xproj[TT * BB * HH];
__device__ float g_h[2][BB * HH];

// bf[h] = sum_e W_ih[h,e] * b_emb[e] + b_ih[h]
__global__ void bfused_kernel(const float* __restrict__ W_ih,
                              const float* __restrict__ b_emb,
                              const float* __restrict__ b_ih,
                              float* __restrict__ out) {
    int h = blockIdx.x * blockDim.x + threadIdx.x;
    if (h >= HH) return;
    float s = b_ih[h];
    const float* row = W_ih + (size_t)h * EE;
    #pragma unroll 4
    for (int e = 0; e < EE; e++) s += row[e] * b_emb[e];
    out[h] = s;
}

// C[M,N] = epilogue( A[M,K] * op(B) [+ bias] )
//   BTRANS=true : B is [N,K] row-major (A @ B^T)
//   BTRANS=false: B is [K,N] row-major (A @ B)
//   EPI=0: C = acc + bias
//   EPI=1: C = tanh(acc + bias + add[m,n])
//   EPI=2: C = acc                     (no bias read)
//   SCATTER: out row m -> (m % TT)*BB + m/TT
template <int BM, int BN, int BK, int TM, int TN, bool BTRANS, int EPI, bool SCATTER>
__global__ __launch_bounds__((BM / TM) * (BN / TN))
void gemm_kernel(const float* __restrict__ A,
                 const float* __restrict__ Bm,
                 const float* __restrict__ bias,
                 const float* __restrict__ add,
                 float* __restrict__ C,
                 int M, int N, int K) {
    constexpr int THREADS = (BM / TM) * (BN / TN);
    static_assert(BM * BK / 4 == THREADS, "A loader: one vec4 per thread");
    static_assert(BN * BK / 4 == THREADS, "B loader: one vec4 per thread");

    __shared__ float As[BK][BM];
    __shared__ float Bs[BK][BN];

    const int tid = threadIdx.x;
    const int bm = blockIdx.y * BM;
    const int bn = blockIdx.x * BN;
    const int tx = tid % (BN / TN);
    const int ty = tid / (BN / TN);

    const int a_row = tid / (BK / 4);
    const int a_kg  = tid % (BK / 4);
    const int bn_kr = tid / (BN / 4);
    const int bn_ng = tid % (BN / 4);

    float acc[TM][TN] = {};

    for (int k0 = 0; k0 < K; k0 += BK) {
        {
            float4 v = *reinterpret_cast<const float4*>(
                &A[(size_t)(bm + a_row) * K + k0 + a_kg * 4]);
            As[a_kg * 4 + 0][a_row] = v.x;
            As[a_kg * 4 + 1][a_row] = v.y;
            As[a_kg * 4 + 2][a_row] = v.z;
            As[a_kg * 4 + 3][a_row] = v.w;
        }
        if (BTRANS) {
            float4 v = *reinterpret_cast<const float4*>(
                &Bm[(size_t)(bn + a_row) * K + k0 + a_kg * 4]);
            Bs[a_kg * 4 + 0][a_row] = v.x;
            Bs[a_kg * 4 + 1][a_row] = v.y;
            Bs[a_kg * 4 + 2][a_row] = v.z;
            Bs[a_kg * 4 + 3][a_row] = v.w;
        } else {
            float4 v = *reinterpret_cast<const float4*>(
                &Bm[(size_t)(k0 + bn_kr) * N + bn + bn_ng * 4]);
            *reinterpret_cast<float4*>(&Bs[bn_kr][bn_ng * 4]) = v;
        }
        __syncthreads();

        #pragma unroll
        for (int k = 0; k < BK; k++) {
            float a[TM], b[TN];
            #pragma unroll
            for (int i = 0; i < TM; i += 4) {
                float4 v = *reinterpret_cast<const float4*>(&As[k][ty * TM + i]);
                a[i] = v.x; a[i + 1] = v.y; a[i + 2] = v.z; a[i + 3] = v.w;
            }
            #pragma unroll
            for (int j = 0; j < TN; j += 4) {
                float4 v = *reinterpret_cast<const float4*>(&Bs[k][tx * TN + j]);
                b[j] = v.x; b[j + 1] = v.y; b[j + 2] = v.z; b[j + 3] = v.w;
            }
            #pragma unroll
            for (int i = 0; i < TM; i++)
                #pragma unroll
                for (int j = 0; j < TN; j++)
                    acc[i][j] += a[i] * b[j];
        }
        __syncthreads();
    }

    #pragma unroll
    for (int i = 0; i < TM; i++) {
        const int m = bm + ty * TM + i;
        size_t om = (size_t)m;
        if (SCATTER) om = (size_t)(m % TT) * BB + (m / TT);
        float* crow = C + om * N;
        const float* arow = (EPI == 1) ? (add + (size_t)m * N) : nullptr;
        #pragma unroll
        for (int j = 0; j < TN; j += 4) {
            const int n = bn + tx * TN + j;
            float4 r;
            r.x = acc[i][j + 0];
            r.y = acc[i][j + 1];
            r.z = acc[i][j + 2];
            r.w = acc[i][j + 3];
            if (EPI != 2) {
                float4 bv = *reinterpret_cast<const float4*>(&bias[n]);
                r.x += bv.x; r.y += bv.y; r.z += bv.z; r.w += bv.w;
            }
            if (EPI == 1) {
                float4 av = *reinterpret_cast<const float4*>(&arow[n]);
                r.x = tanhf(r.x + av.x);
                r.y = tanhf(r.y + av.y);
                r.z = tanhf(r.z + av.z);
                r.w = tanhf(r.w + av.w);
            }
            *reinterpret_cast<float4*>(&crow[n]) = r;
        }
    }
}

extern "C" void kernel_launch(void* const* d_in, const int* in_sizes, int n_in,
                              void* d_out, int out_size) {
    const float* msg   = (const float*)d_in[0];  // [B, T, V]
    const float* W_emb = (const float*)d_in[1];  // [E, V]
    const float* b_emb = (const float*)d_in[2];  // [E]
    const float* W_ih  = (const float*)d_in[3];  // [H, E]
    const float* b_ih  = (const float*)d_in[4];  // [H]
    const float* W_hh  = (const float*)d_in[5];  // [H, H]
    const float* b_hh  = (const float*)d_in[6];  // [H]
    const float* W_out = (const float*)d_in[7];  // [O, H]
    const float* b_out = (const float*)d_in[8];  // [O]
    float* out = (float*)d_out;                  // [B, O]

    float *wfused, *bfused, *xproj, *h0;
    cudaGetSymbolAddress((void**)&wfused, g_wfused);
    cudaGetSymbolAddress((void**)&bfused, g_bfused);
    cudaGetSymbolAddress((void**)&xproj,  g_xproj);
    cudaGetSymbolAddress((void**)&h0,     g_h);
    float* h1 = h0 + (size_t)BB * HH;

    cudaMemsetAsync(h0, 0, (size_t)BB * HH * sizeof(float), 0);

    bfused_kernel<<<(HH + 255) / 256, 256>>>(W_ih, b_emb, b_ih, bfused);

    // W_fused[H,V] = W_ih[H,E] @ W_emb[E,V]
    {
        dim3 grid(VV / 128, HH / 128);
        gemm_kernel<128, 128, 8, 8, 8, false, 2, false>
            <<<grid, 256>>>(W_ih, W_emb, nullptr, nullptr, wfused, HH, VV, EE);
    }

    // x_proj[T,B,H] = msg @ W_fused^T + b_fused  (scatter [B*T]->[T,B])
    {
        dim3 grid(HH / 128, (BB * TT) / 128);
        gemm_kernel<128, 128, 8, 8, 8, true, 0, true>
            <<<grid, 256>>>(msg, wfused, bfused, nullptr, xproj,
                            BB * TT, HH, VV);
    }

    // h_{t+1} = tanh(x_t + h_t @ W_hh^T + b_hh)
    float* hc = h0;
    float* hn = h1;
    for (int t = 0; t < TT; t++) {
        dim3 grid(HH / 64, BB / 64);
        gemm_kernel<64, 64, 16, 4, 4, true, 1, false>
            <<<grid, 256>>>(hc, W_hh, b_hh, xproj + (size_t)t * BB * HH, hn,
                            BB, HH, HH);
        float* tmp = hc; hc = hn; hn = tmp;
    }

    // out = h_T @ W_out^T + b_out
    {
        dim3 grid(OO / 64, BB / 64);
        gemm_kernel<64, 64, 16, 4, 4, true, 0, false>
            <<<grid, 256>>>(hc, W_out, b_out, nullptr, out, BB, OO, HH);
    }
}

// round 2
// speedup vs baseline: 1.9028x; 1.9028x over previous
#include <cuda_runtime.h>
#include <cuda_bf16.h>
#include <cstddef>
#include <cstdint>

#define BB   1024
#define TT   32
#define VV   1024
#define EE   512
#define HH   1024
#define OO   1024

// ---------------- scratch (static device globals; no runtime alloc) --------
__device__ float g_wfused[HH * VV];                 // W_ih @ W_emb  [H, V]
__device__ float g_bfused[HH];                      // W_ih @ b_emb + b_ih
__device__ float g_xproj[TT * BB * HH];             // [T, B, H] fp32
__device__ __nv_bfloat16 g_msg_hi[BB * TT * VV];
__device__ __nv_bfloat16 g_msg_lo[BB * TT * VV];
__device__ __nv_bfloat16 g_wf_hi[HH * VV];
__device__ __nv_bfloat16 g_wf_lo[HH * VV];
__device__ __nv_bfloat16 g_whh_hi[HH * HH];
__device__ __nv_bfloat16 g_whh_lo[HH * HH];
__device__ __nv_bfloat16 g_wout_hi[OO * HH];
__device__ __nv_bfloat16 g_wout_lo[OO * HH];
__device__ __nv_bfloat16 g_h_hi[2][BB * HH];
__device__ __nv_bfloat16 g_h_lo[2][BB * HH];

// ---------------------------------------------------------------------------
// bf[h] = sum_e W_ih[h,e] * b_emb[e] + b_ih[h]
// ---------------------------------------------------------------------------
__global__ void bfused_kernel(const float* __restrict__ W_ih,
                              const float* __restrict__ b_emb,
                              const float* __restrict__ b_ih,
                              float* __restrict__ out) {
    int h = blockIdx.x * blockDim.x + threadIdx.x;
    if (h >= HH) return;
    float s = b_ih[h];
    const float* row = W_ih + (size_t)h * EE;
    #pragma unroll 4
    for (int e = 0; e < EE; e++) s += row[e] * b_emb[e];
    out[h] = s;
}

// ---------------------------------------------------------------------------
// fp32 SGEMM (only for the tiny W_fused = W_ih @ W_emb precompute, 1.1 GF)
//   C[M,N] = A[M,K] * B[K,N]   (B row-major [K,N])
// ---------------------------------------------------------------------------
__global__ __launch_bounds__(256)
void sgemm_nn_kernel(const float* __restrict__ A,
                     const float* __restrict__ Bm,
                     float* __restrict__ C,
                     int M, int N, int K) {
    constexpr int BM = 128, BN = 128, BK = 8, TM = 8, TN = 8;
    __shared__ float As[BK][BM];
    __shared__ float Bs[BK][BN];

    const int tid = threadIdx.x;
    const int bm = blockIdx.y * BM;
    const int bn = blockIdx.x * BN;
    const int tx = tid % (BN / TN);
    const int ty = tid / (BN / TN);

    const int a_row = tid / (BK / 4);
    const int a_kg  = tid % (BK / 4);
    const int b_kr  = tid / (BN / 4);
    const int b_ng  = tid % (BN / 4);

    float acc[TM][TN] = {};

    for (int k0 = 0; k0 < K; k0 += BK) {
        {
            float4 v = *reinterpret_cast<const float4*>(
                &A[(size_t)(bm + a_row) * K + k0 + a_kg * 4]);
            As[a_kg * 4 + 0][a_row] = v.x;
            As[a_kg * 4 + 1][a_row] = v.y;
            As[a_kg * 4 + 2][a_row] = v.z;
            As[a_kg * 4 + 3][a_row] = v.w;
        }
        {
            float4 v = *reinterpret_cast<const float4*>(
                &Bm[(size_t)(k0 + b_kr) * N + bn + b_ng * 4]);
            *reinterpret_cast<float4*>(&Bs[b_kr][b_ng * 4]) = v;
        }
        __syncthreads();
        #pragma unroll
        for (int k = 0; k < BK; k++) {
            float a[TM], b[TN];
            #pragma unroll
            for (int i = 0; i < TM; i += 4) {
                float4 v = *reinterpret_cast<const float4*>(&As[k][ty * TM + i]);
                a[i] = v.x; a[i+1] = v.y; a[i+2] = v.z; a[i+3] = v.w;
            }
            #pragma unroll
            for (int j = 0; j < TN; j += 4) {
                float4 v = *reinterpret_cast<const float4*>(&Bs[k][tx * TN + j]);
                b[j] = v.x; b[j+1] = v.y; b[j+2] = v.z; b[j+3] = v.w;
            }
            #pragma unroll
            for (int i = 0; i < TM; i++)
                #pragma unroll
                for (int j = 0; j < TN; j++)
                    acc[i][j] += a[i] * b[j];
        }
        __syncthreads();
    }
    #pragma unroll
    for (int i = 0; i < TM; i++) {
        float* crow = C + (size_t)(bm + ty * TM + i) * N;
        #pragma unroll
        for (int j = 0; j < TN; j += 4) {
            float4 r = { acc[i][j], acc[i][j+1], acc[i][j+2], acc[i][j+3] };
            *reinterpret_cast<float4*>(&crow[bn + tx * TN + j]) = r;
        }
    }
}

// ---------------------------------------------------------------------------
// fp32 -> (bf16 hi, bf16 lo) split: x ~= hi + lo, |err| ~ 2^-17 |x|
// ---------------------------------------------------------------------------
__global__ void split_kernel(const float* __restrict__ in,
                             __nv_bfloat16* __restrict__ hi,
                             __nv_bfloat16* __restrict__ lo,
                             int n4) {   // n4 = n/4
    int idx = blockIdx.x * blockDim.x + threadIdx.x;
    for (; idx < n4; idx += gridDim.x * blockDim.x) {
        float4 v = reinterpret_cast<const float4*>(in)[idx];
        __nv_bfloat16 h0 = __float2bfloat16(v.x);
        __nv_bfloat16 h1 = __float2bfloat16(v.y);
        __nv_bfloat16 h2 = __float2bfloat16(v.z);
        __nv_bfloat16 h3 = __float2bfloat16(v.w);
        __nv_bfloat162 hp0; hp0.x = h0; hp0.y = h1;
        __nv_bfloat162 hp1; hp1.x = h2; hp1.y = h3;
        __nv_bfloat162 lp0;
        lp0.x = __float2bfloat16(v.x - __bfloat162float(h0));
        lp0.y = __float2bfloat16(v.y - __bfloat162float(h1));
        __nv_bfloat162 lp1;
        lp1.x = __float2bfloat16(v.z - __bfloat162float(h2));
        lp1.y = __float2bfloat16(v.w - __bfloat162float(h3));
        reinterpret_cast<__nv_bfloat162*>(hi)[idx * 2 + 0] = hp0;
        reinterpret_cast<__nv_bfloat162*>(hi)[idx * 2 + 1] = hp1;
        reinterpret_cast<__nv_bfloat162*>(lo)[idx * 2 + 0] = lp0;
        reinterpret_cast<__nv_bfloat162*>(lo)[idx * 2 + 1] = lp1;
    }
}

// ---------------------------------------------------------------------------
// Tensor-core split-bf16 GEMM:  C[M,N] ~= A[M,K] @ B[N,K]^T  (fp32 accuracy)
//   acc = Ahi*Bhi + Ahi*Blo + Alo*Bhi   (fp32 accumulate in HMMA)
//   EPI=0: Cf = acc + bias            (SCATTER: row m -> (m%TT)*BB + m/TT)
//   EPI=1: h  = tanh(acc + bias + add[m,n]) -> written as (Chi, Clo) split
// Tiles: CTA 128x64xK, BK=32, 8 warps (2x4), warp tile 64x16.
// ---------------------------------------------------------------------------
__device__ __forceinline__ void ldsm_x4(uint32_t* r, uint32_t addr) {
    asm volatile("ldmatrix.sync.aligned.m8n8.x4.shared.b16 {%0,%1,%2,%3}, [%4];"
                 : "=r"(r[0]), "=r"(r[1]), "=r"(r[2]), "=r"(r[3]) : "r"(addr));
}

__device__ __forceinline__ void mma_bf16(float* d, const uint32_t* a, const uint32_t* b) {
    asm volatile("mma.sync.aligned.m16n8k16.row.col.f32.bf16.bf16.f32 "
                 "{%0,%1,%2,%3}, {%4,%5,%6,%7}, {%8,%9}, {%0,%1,%2,%3};"
                 : "+f"(d[0]), "+f"(d[1]), "+f"(d[2]), "+f"(d[3])
                 : "r"(a[0]), "r"(a[1]), "r"(a[2]), "r"(a[3]),
                   "r"(b[0]), "r"(b[1]));
}

template <int EPI, bool SCATTER>
__global__ __launch_bounds__(256)
void mma_gemm_kernel(const __nv_bfloat16* __restrict__ Ahi,
                     const __nv_bfloat16* __restrict__ Alo,
                     const __nv_bfloat16* __restrict__ Bhi,
                     const __nv_bfloat16* __restrict__ Blo,
                     const float* __restrict__ bias,
                     const float* __restrict__ add,
                     float* __restrict__ Cf,
                     __nv_bfloat16* __restrict__ Chi,
                     __nv_bfloat16* __restrict__ Clo,
                     int M, int N, int K) {
    constexpr int BM = 128, BN = 64, BK = 32, LDT = BK + 8;

    __shared__ __align__(16) __nv_bfloat16 sAhi[BM * LDT];
    __shared__ __align__(16) __nv_bfloat16 sAlo[BM * LDT];
    __shared__ __align__(16) __nv_bfloat16 sBhi[BN * LDT];
    __shared__ __align__(16) __nv_bfloat16 sBlo[BN * LDT];

    const int tid  = threadIdx.x;
    const int lane = tid & 31;
    const int wid  = tid >> 5;
    const int bm = blockIdx.y * BM;
    const int bn = blockIdx.x * BN;
    const int wm = (wid >> 2) * 64;   // warp row tile (0 or 64)
    const int wn = (wid & 3) * 16;    // warp col tile (0..48)

    // ldmatrix per-lane offsets (elements)
    const int a_row = wm + (lane & 7) + ((lane >> 3) & 1) * 8;
    const int a_col = (lane >> 4) * 8;
    const int b_row = wn + (lane >> 4) * 8 + (lane & 7);
    const int b_col = ((lane >> 3) & 1) * 8;

    const uint32_t aAhi = (uint32_t)__cvta_generic_to_shared(sAhi) + (a_row * LDT + a_col) * 2;
    const uint32_t aAlo = (uint32_t)__cvta_generic_to_shared(sAlo) + (a_row * LDT + a_col) * 2;
    const uint32_t aBhi = (uint32_t)__cvta_generic_to_shared(sBhi) + (b_row * LDT + b_col) * 2;
    const uint32_t aBlo = (uint32_t)__cvta_generic_to_shared(sBlo) + (b_row * LDT + b_col) * 2;

    // loader coords: A 128x32 = 512 16B-segs (2/thread); B 64x32 = 256 (1/thread)
    const int a_r0 = tid >> 2;            const int a_c0 = (tid & 3) * 8;
    const int a_r1 = (tid + 256) >> 2;    const int a_c1 = a_c0;
    const int b_r  = tid >> 2;            const int b_c  = (tid & 3) * 8;

    float acc[4][2][4] = {};

    for (int k0 = 0; k0 < K; k0 += BK) {
        *reinterpret_cast<uint4*>(&sAhi[a_r0 * LDT + a_c0]) =
            *reinterpret_cast<const uint4*>(&Ahi[(size_t)(bm + a_r0) * K + k0 + a_c0]);
        *reinterpret_cast<uint4*>(&sAlo[a_r0 * LDT + a_c0]) =
            *reinterpret_cast<const uint4*>(&Alo[(size_t)(bm + a_r0) * K + k0 + a_c0]);
        *reinterpret_cast<uint4*>(&sAhi[a_r1 * LDT + a_c1]) =
            *reinterpret_cast<const uint4*>(&Ahi[(size_t)(bm + a_r1) * K + k0 + a_c1]);
        *reinterpret_cast<uint4*>(&sAlo[a_r1 * LDT + a_c1]) =
            *reinterpret_cast<const uint4*>(&Alo[(size_t)(bm + a_r1) * K + k0 + a_c1]);
        *reinterpret_cast<uint4*>(&sBhi[b_r * LDT + b_c]) =
            *reinterpret_cast<const uint4*>(&Bhi[(size_t)(bn + b_r) * K + k0 + b_c]);
        *reinterpret_cast<uint4*>(&sBlo[b_r * LDT + b_c]) =
            *reinterpret_cast<const uint4*>(&Blo[(size_t)(bn + b_r) * K + k0 + b_c]);
        __syncthreads();

        #pragma unroll
        for (int kk = 0; kk < BK; kk += 16) {
            uint32_t ah[4][4], al[4][4], bh[4], bl[4];
            #pragma unroll
            for (int i = 0; i < 4; i++) {
                ldsm_x4(ah[i], aAhi + (i * 16 * LDT + kk) * 2);
                ldsm_x4(al[i], aAlo + (i * 16 * LDT + kk) * 2);
            }
            ldsm_x4(bh, aBhi + kk * 2);
            ldsm_x4(bl, aBlo + kk * 2);
            #pragma unroll
            for (int i = 0; i < 4; i++) {
                #pragma unroll
                for (int j = 0; j < 2; j++) {
                    mma_bf16(acc[i][j], ah[i], &bh[j * 2]);
                    mma_bf16(acc[i][j], ah[i], &bl[j * 2]);
                    mma_bf16(acc[i][j], al[i], &bh[j * 2]);
                }
            }
        }
        __syncthreads();
    }

    // epilogue: C frag -> (row = lane/4 (+8), col = 2*(lane%4) (+1))
    const int crow = lane >> 2;
    const int ccol = (lane & 3) * 2;
    #pragma unroll
    for (int i = 0; i < 4; i++) {
        #pragma unroll
        for (int j = 0; j < 2; j++) {
            #pragma unroll
            for (int half = 0; half < 2; half++) {
                const int m = bm + wm + i * 16 + crow + half * 8;
                const int n = bn + wn + j * 8 + ccol;
                float v0 = acc[i][j][half * 2 + 0];
                float v1 = acc[i][j][half * 2 + 1];
                if (EPI == 0) {
                    v0 += bias[n];
                    v1 += bias[n + 1];
                    size_t om = (size_t)m;
                    if (SCATTER) om = (size_t)(m % TT) * BB + (m / TT);
                    float2 r = { v0, v1 };
                    *reinterpret_cast<float2*>(&Cf[om * N + n]) = r;
                } else {
                    const float* arow = add + (size_t)m * N;
                    v0 = tanhf(v0 + bias[n]     + arow[n]);
                    v1 = tanhf(v1 + bias[n + 1] + arow[n + 1]);
                    __nv_bfloat16 h0 = __float2bfloat16(v0);
                    __nv_bfloat16 h1 = __float2bfloat16(v1);
                    __nv_bfloat162 hp; hp.x = h0; hp.y = h1;
                    __nv_bfloat162 lp;
                    lp.x = __float2bfloat16(v0 - __bfloat162float(h0));
                    lp.y = __float2bfloat16(v1 - __bfloat162float(h1));
                    *reinterpret_cast<__nv_bfloat162*>(&Chi[(size_t)m * N + n]) = hp;
                    *reinterpret_cast<__nv_bfloat162*>(&Clo[(size_t)m * N + n]) = lp;
                }
            }
        }
    }
}

// ---------------------------------------------------------------------------
extern "C" void kernel_launch(void* const* d_in, const int* in_sizes, int n_in,
                              void* d_out, int out_size) {
    const float* msg   = (const float*)d_in[0];  // [B, T, V]
    const float* W_emb = (const float*)d_in[1];  // [E, V]
    const float* b_emb = (const float*)d_in[2];  // [E]
    const float* W_ih  = (const float*)d_in[3];  // [H, E]
    const float* b_ih  = (const float*)d_in[4];  // [H]
    const float* W_hh  = (const float*)d_in[5];  // [H, H]
    const float* b_hh  = (const float*)d_in[6];  // [H]
    const float* W_out = (const float*)d_in[7];  // [O, H]
    const float* b_out = (const float*)d_in[8];  // [O]
    float* out = (float*)d_out;                  // [B, O]

    float *wfused, *bfused, *xproj;
    __nv_bfloat16 *msg_hi, *msg_lo, *wf_hi, *wf_lo, *whh_hi, *whh_lo,
                  *wout_hi, *wout_lo, *h_hi, *h_lo;
    cudaGetSymbolAddress((void**)&wfused,  g_wfused);
    cudaGetSymbolAddress((void**)&bfused,  g_bfused);
    cudaGetSymbolAddress((void**)&xproj,   g_xproj);
    cudaGetSymbolAddress((void**)&msg_hi,  g_msg_hi);
    cudaGetSymbolAddress((void**)&msg_lo,  g_msg_lo);
    cudaGetSymbolAddress((void**)&wf_hi,   g_wf_hi);
    cudaGetSymbolAddress((void**)&wf_lo,   g_wf_lo);
    cudaGetSymbolAddress((void**)&whh_hi,  g_whh_hi);
    cudaGetSymbolAddress((void**)&whh_lo,  g_whh_lo);
    cudaGetSymbolAddress((void**)&wout_hi, g_wout_hi);
    cudaGetSymbolAddress((void**)&wout_lo, g_wout_lo);
    cudaGetSymbolAddress((void**)&h_hi,    g_h_hi);
    cudaGetSymbolAddress((void**)&h_lo,    g_h_lo);

    // h(0) = 0  (hi and lo, ping buffer 0)
    cudaMemsetAsync(h_hi, 0, (size_t)BB * HH * sizeof(__nv_bfloat16), 0);
    cudaMemsetAsync(h_lo, 0, (size_t)BB * HH * sizeof(__nv_bfloat16), 0);

    bfused_kernel<<<(HH + 255) / 256, 256>>>(W_ih, b_emb, b_ih, bfused);

    // W_fused[H,V] = W_ih[H,E] @ W_emb[E,V]   (fp32, tiny)
    {
        dim3 grid(VV / 128, HH / 128);
        sgemm_nn_kernel<<<grid, 256>>>(W_ih, W_emb, wfused, HH, VV, EE);
    }

    // splits
    split_kernel<<<2048, 256>>>(wfused, wf_hi, wf_lo, HH * VV / 4);
    split_kernel<<<8192, 256>>>(msg, msg_hi, msg_lo, BB * TT * VV / 4);
    split_kernel<<<2048, 256>>>(W_hh, whh_hi, whh_lo, HH * HH / 4);
    split_kernel<<<2048, 256>>>(W_out, wout_hi, wout_lo, OO * HH / 4);

    // x_proj[T,B,H] = msg @ W_fused^T + b_fused  (scatter rows [B*T]->[T,B])
    {
        dim3 grid(HH / 64, (BB * TT) / 128);
        mma_gemm_kernel<0, true><<<grid, 256>>>(
            msg_hi, msg_lo, wf_hi, wf_lo, bfused, nullptr,
            xproj, nullptr, nullptr, BB * TT, HH, VV);
    }

    // recurrence: h_{t+1} = tanh(x_t + h_t @ W_hh^T + b_hh)
    __nv_bfloat16* hc_hi = h_hi;
    __nv_bfloat16* hc_lo = h_lo;
    __nv_bfloat16* hn_hi = h_hi + (size_t)BB * HH;
    __nv_bfloat16* hn_lo = h_lo + (size_t)BB * HH;
    for (int t = 0; t < TT; t++) {
        dim3 grid(HH / 64, BB / 128);
        mma_gemm_kernel<1, false><<<grid, 256>>>(
            hc_hi, hc_lo, whh_hi, whh_lo, b_hh, xproj + (size_t)t * BB * HH,
            nullptr, hn_hi, hn_lo, BB, HH, HH);
        __nv_bfloat16* tmp;
        tmp = hc_hi; hc_hi = hn_hi; hn_hi = tmp;
        tmp = hc_lo; hc_lo = hn_lo; hn_lo = tmp;
    }

    // out = h_T @ W_out^T + b_out   (fp32 result)
    {
        dim3 grid(OO / 64, BB / 128);
        mma_gemm_kernel<0, false><<<grid, 256>>>(
            hc_hi, hc_lo, wout_hi, wout_lo, b_out, nullptr,
            out, nullptr, nullptr, BB, OO, HH);
    }
}

// round 4
// speedup vs baseline: 2.5469x; 1.3385x over previous
#include <cuda_runtime.h>
#include <cuda_bf16.h>
#include <cstddef>
#include <cstdint>

#define BB   1024
#define TT   32
#define VV   1024
#define EE   512
#define HH   1024
#define OO   1024

// ---------------- device scratch (no runtime allocation) -------------------
__device__ float g_bfused[HH];
__device__ float g_xproj[TT * BB * HH];
__device__ __nv_bfloat16 g_msg_hi[BB * TT * VV];
__device__ __nv_bfloat16 g_msg_lo[BB * TT * VV];
__device__ __nv_bfloat16 g_wembT_hi[VV * EE];
__device__ __nv_bfloat16 g_wembT_lo[VV * EE];
__device__ __nv_bfloat16 g_wih_hi[HH * EE];
__device__ __nv_bfloat16 g_wih_lo[HH * EE];
__device__ __nv_bfloat16 g_wf_hi[HH * VV];
__device__ __nv_bfloat16 g_wf_lo[HH * VV];
__device__ __nv_bfloat16 g_whh_hi[HH * HH];
__device__ __nv_bfloat16 g_whh_lo[HH * HH];
__device__ __nv_bfloat16 g_wout_hi[OO * HH];
__device__ __nv_bfloat16 g_wout_lo[OO * HH];
__device__ __nv_bfloat16 g_h_hi[2][BB * HH];
__device__ __nv_bfloat16 g_h_lo[2][BB * HH];

// ---------------- helpers ---------------------------------------------------
__device__ __forceinline__ void bf16_split(float x, __nv_bfloat16& h, __nv_bfloat16& l) {
    h = __float2bfloat16(x);
    l = __float2bfloat16(x - __bfloat162float(h));
}

__device__ __forceinline__ void ldsm_x4(uint32_t* r, uint32_t addr) {
    asm volatile("ldmatrix.sync.aligned.m8n8.x4.shared.b16 {%0,%1,%2,%3}, [%4];"
                 : "=r"(r[0]), "=r"(r[1]), "=r"(r[2]), "=r"(r[3]) : "r"(addr));
}

__device__ __forceinline__ void mma_bf16(float* d, const uint32_t* a, const uint32_t* b) {
    asm volatile("mma.sync.aligned.m16n8k16.row.col.f32.bf16.bf16.f32 "
                 "{%0,%1,%2,%3}, {%4,%5,%6,%7}, {%8,%9}, {%0,%1,%2,%3};"
                 : "+f"(d[0]), "+f"(d[1]), "+f"(d[2]), "+f"(d[3])
                 : "r"(a[0]), "r"(a[1]), "r"(a[2]), "r"(a[3]),
                   "r"(b[0]), "r"(b[1]));
}

__device__ __forceinline__ void cp16(uint32_t dst, const void* src) {
    asm volatile("cp.async.cg.shared.global [%0], [%1], 16;" :: "r"(dst), "l"(src));
}
#define CP_COMMIT() asm volatile("cp.async.commit_group;" ::: "memory")
#define CP_WAIT(n)  asm volatile("cp.async.wait_group %0;" :: "n"(n) : "memory")

// ---------------------------------------------------------------------------
// 3-stage cp.async pipelined split-bf16 tensor-core GEMM
//   C[M,N] ~= A[M,K] @ B[N,K]^T  via  Ahi*Bhi + Ahi*Blo + Alo*Bhi (fp32 acc)
//   EPI 0: Cf  = acc + bias           (SCATTER: row m -> (m%TT)*BB + m/TT)
//   EPI 1: tanh(acc + bias + add) -> (Chi, Clo) bf16 split
//   EPI 2: acc -> (Chi, Clo) bf16 split (no bias)
// CTA tile 128x64, BK=32, 8 warps (2m x 4n), warp tile 64x16.
// M,N mult of tile, K mult of 32.
// ---------------------------------------------------------------------------
constexpr int BM = 128, BN = 64, BK = 32, LDT = BK + 8, STAGES = 3;
constexpr int A_ELE = BM * LDT;              // 5120 elems per A tile
constexpr int B_ELE = BN * LDT;              // 2560
constexpr int STG_ELE = 2 * A_ELE + 2 * B_ELE;  // 15360 elems = 30720 B
constexpr int SMEM_BYTES = STAGES * STG_ELE * 2; // 92160 B
// tile offsets inside a stage (elements)
#define OFF_AHI 0
#define OFF_ALO (A_ELE)
#define OFF_BHI (2 * A_ELE)
#define OFF_BLO (2 * A_ELE + B_ELE)

template <int EPI, bool SCATTER>
__global__ __launch_bounds__(256)
void mma_gemm(const __nv_bfloat16* __restrict__ Ahi,
              const __nv_bfloat16* __restrict__ Alo,
              const __nv_bfloat16* __restrict__ Bhi,
              const __nv_bfloat16* __restrict__ Blo,
              const float* __restrict__ bias,
              const float* __restrict__ add,
              float* __restrict__ Cf,
              __nv_bfloat16* __restrict__ Chi,
              __nv_bfloat16* __restrict__ Clo,
              int M, int N, int K) {
    extern __shared__ __align__(16) __nv_bfloat16 smem[];
    const uint32_t sb = (uint32_t)__cvta_generic_to_shared(smem);

    const int tid  = threadIdx.x;
    const int lane = tid & 31;
    const int wid  = tid >> 5;
    const int bm = blockIdx.y * BM;
    const int bn = blockIdx.x * BN;
    const int wm = (wid >> 2) * 64;
    const int wn = (wid & 3) * 16;
    const int CH = K / BK;

    // loader coords: A tile 128x32 -> 512 16B segs (2/thread); B 64x32 -> 256 (1/thread)
    const int a_r0 = tid >> 2;          const int a_c = (tid & 3) * 8;
    const int a_r1 = (tid + 256) >> 2;
    const int b_r  = tid >> 2;

    auto load_chunk = [&](int k0, int s) {
        const uint32_t st = sb + (uint32_t)(s * STG_ELE) * 2;
        const size_t ga0 = (size_t)(bm + a_r0) * K + k0 + a_c;
        const size_t ga1 = (size_t)(bm + a_r1) * K + k0 + a_c;
        const size_t gb  = (size_t)(bn + b_r ) * K + k0 + a_c;
        const uint32_t d0 = (uint32_t)(a_r0 * LDT + a_c) * 2;
        const uint32_t d1 = (uint32_t)(a_r1 * LDT + a_c) * 2;
        const uint32_t db = (uint32_t)(b_r  * LDT + a_c) * 2;
        cp16(st + OFF_AHI * 2 + d0, Ahi + ga0);
        cp16(st + OFF_AHI * 2 + d1, Ahi + ga1);
        cp16(st + OFF_ALO * 2 + d0, Alo + ga0);
        cp16(st + OFF_ALO * 2 + d1, Alo + ga1);
        cp16(st + OFF_BHI * 2 + db, Bhi + gb);
        cp16(st + OFF_BLO * 2 + db, Blo + gb);
    };

    // ldmatrix per-lane base offsets (elements within a tile)
    const int a_row = wm + (lane & 7) + ((lane >> 3) & 1) * 8;
    const int a_col = (lane >> 4) * 8;
    const int b_row = wn + (lane >> 4) * 8 + (lane & 7);
    const int b_col = ((lane >> 3) & 1) * 8;
    const uint32_t aoff = (uint32_t)(a_row * LDT + a_col) * 2;
    const uint32_t boff = (uint32_t)(b_row * LDT + b_col) * 2;

    float acc[4][2][4] = {};

    // prologue: prefetch first STAGES-1 chunks
    #pragma unroll
    for (int s = 0; s < STAGES - 1; s++) {
        load_chunk(s * BK, s);
        CP_COMMIT();
    }

    for (int c = 0; c < CH; c++) {
        CP_WAIT(STAGES - 2);
        __syncthreads();

        const int pc = c + STAGES - 1;
        if (pc < CH) load_chunk(pc * BK, pc % STAGES);
        CP_COMMIT();

        const uint32_t st = sb + (uint32_t)((c % STAGES) * STG_ELE) * 2;
        const uint32_t aAhi = st + OFF_AHI * 2 + aoff;
        const uint32_t aAlo = st + OFF_ALO * 2 + aoff;
        const uint32_t aBhi = st + OFF_BHI * 2 + boff;
        const uint32_t aBlo = st + OFF_BLO * 2 + boff;

        #pragma unroll
        for (int kk = 0; kk < BK; kk += 16) {
            uint32_t ah[4][4], al[4][4], bh[4], bl[4];
            #pragma unroll
            for (int i = 0; i < 4; i++) {
                ldsm_x4(ah[i], aAhi + (uint32_t)(i * 16 * LDT + kk) * 2);
                ldsm_x4(al[i], aAlo + (uint32_t)(i * 16 * LDT + kk) * 2);
            }
            ldsm_x4(bh, aBhi + (uint32_t)kk * 2);
            ldsm_x4(bl, aBlo + (uint32_t)kk * 2);
            #pragma unroll
            for (int i = 0; i < 4; i++) {
                #pragma unroll
                for (int j = 0; j < 2; j++) {
                    mma_bf16(acc[i][j], ah[i], &bh[j * 2]);
                    mma_bf16(acc[i][j], ah[i], &bl[j * 2]);
                    mma_bf16(acc[i][j], al[i], &bh[j * 2]);
                }
            }
        }
    }

    // ---- epilogue (fragment: row = lane/4 (+8), col = 2*(lane%4) (+1)) ----
    const int crow = lane >> 2;
    const int ccol = (lane & 3) * 2;
    #pragma unroll
    for (int i = 0; i < 4; i++) {
        #pragma unroll
        for (int j = 0; j < 2; j++) {
            #pragma unroll
            for (int half = 0; half < 2; half++) {
                const int m = bm + wm + i * 16 + crow + half * 8;
                const int n = bn + wn + j * 8 + ccol;
                float v0 = acc[i][j][half * 2 + 0];
                float v1 = acc[i][j][half * 2 + 1];
                if (EPI == 0) {
                    v0 += bias[n];
                    v1 += bias[n + 1];
                    size_t om = (size_t)m;
                    if (SCATTER) om = (size_t)(m % TT) * BB + (size_t)(m / TT);
                    float2 r = { v0, v1 };
                    *reinterpret_cast<float2*>(&Cf[om * N + n]) = r;
                } else if (EPI == 1) {
                    const float* arow = add + (size_t)m * N;
                    v0 = tanhf(v0 + bias[n]     + arow[n]);
                    v1 = tanhf(v1 + bias[n + 1] + arow[n + 1]);
                    __nv_bfloat162 hp, lp;
                    bf16_split(v0, hp.x, lp.x);
                    bf16_split(v1, hp.y, lp.y);
                    *reinterpret_cast<__nv_bfloat162*>(&Chi[(size_t)m * N + n]) = hp;
                    *reinterpret_cast<__nv_bfloat162*>(&Clo[(size_t)m * N + n]) = lp;
                } else {
                    __nv_bfloat162 hp, lp;
                    bf16_split(v0, hp.x, lp.x);
                    bf16_split(v1, hp.y, lp.y);
                    *reinterpret_cast<__nv_bfloat162*>(&Chi[(size_t)m * N + n]) = hp;
                    *reinterpret_cast<__nv_bfloat162*>(&Clo[(size_t)m * N + n]) = lp;
                }
            }
        }
    }
}

// ---------------------------------------------------------------------------
// bf[h] = sum_e W_ih[h,e] * b_emb[e] + b_ih[h]
// ---------------------------------------------------------------------------
__global__ void bfused_kernel(const float* __restrict__ W_ih,
                              const float* __restrict__ b_emb,
                              const float* __restrict__ b_ih,
                              float* __restrict__ out) {
    int h = blockIdx.x * blockDim.x + threadIdx.x;
    if (h >= HH) return;
    float s = b_ih[h];
    const float* row = W_ih + (size_t)h * EE;
    #pragma unroll 4
    for (int e = 0; e < EE; e++) s += row[e] * b_emb[e];
    out[h] = s;
}

// fp32 -> (bf16 hi, lo) elementwise split
__global__ void split_kernel(const float* __restrict__ in,
                             __nv_bfloat16* __restrict__ hi,
                             __nv_bfloat16* __restrict__ lo,
                             int n4) {
    int idx = blockIdx.x * blockDim.x + threadIdx.x;
    for (; idx < n4; idx += gridDim.x * blockDim.x) {
        float4 v = reinterpret_cast<const float4*>(in)[idx];
        __nv_bfloat162 hp0, hp1, lp0, lp1;
        bf16_split(v.x, hp0.x, lp0.x);
        bf16_split(v.y, hp0.y, lp0.y);
        bf16_split(v.z, hp1.x, lp1.x);
        bf16_split(v.w, hp1.y, lp1.y);
        reinterpret_cast<__nv_bfloat162*>(hi)[idx * 2 + 0] = hp0;
        reinterpret_cast<__nv_bfloat162*>(hi)[idx * 2 + 1] = hp1;
        reinterpret_cast<__nv_bfloat162*>(lo)[idx * 2 + 0] = lp0;
        reinterpret_cast<__nv_bfloat162*>(lo)[idx * 2 + 1] = lp1;
    }
}

// W_emb [E,V] fp32 -> transposed splits [V,E] bf16 hi/lo
__global__ void transpose_split_kernel(const float* __restrict__ in,
                                       __nv_bfloat16* __restrict__ hi,
                                       __nv_bfloat16* __restrict__ lo) {
    __shared__ float t[32][33];
    const int v0 = blockIdx.x * 32, e0 = blockIdx.y * 32;
    for (int i = threadIdx.y; i < 32; i += 8)
        t[i][threadIdx.x] = in[(size_t)(e0 + i) * VV + v0 + threadIdx.x];
    __syncthreads();
    for (int i = threadIdx.y; i < 32; i += 8) {
        float x = t[threadIdx.x][i];
        __nv_bfloat16 h, l;
        bf16_split(x, h, l);
        size_t o = (size_t)(v0 + i) * EE + e0 + threadIdx.x;
        hi[o] = h;
        lo[o] = l;
    }
}

// ---------------------------------------------------------------------------
extern "C" void kernel_launch(void* const* d_in, const int* in_sizes, int n_in,
                              void* d_out, int out_size) {
    const float* msg   = (const float*)d_in[0];
    const float* W_emb = (const float*)d_in[1];
    const float* b_emb = (const float*)d_in[2];
    const float* W_ih  = (const float*)d_in[3];
    const float* b_ih  = (const float*)d_in[4];
    const float* W_hh  = (const float*)d_in[5];
    const float* b_hh  = (const float*)d_in[6];
    const float* W_out = (const float*)d_in[7];
    const float* b_out = (const float*)d_in[8];
    float* out = (float*)d_out;

    float *bfused, *xproj;
    __nv_bfloat16 *msg_hi, *msg_lo, *wembT_hi, *wembT_lo, *wih_hi, *wih_lo,
                  *wf_hi, *wf_lo, *whh_hi, *whh_lo, *wout_hi, *wout_lo, *h_hi, *h_lo;
    cudaGetSymbolAddress((void**)&bfused,   g_bfused);
    cudaGetSymbolAddress((void**)&xproj,    g_xproj);
    cudaGetSymbolAddress((void**)&msg_hi,   g_msg_hi);
    cudaGetSymbolAddress((void**)&msg_lo,   g_msg_lo);
    cudaGetSymbolAddress((void**)&wembT_hi, g_wembT_hi);
    cudaGetSymbolAddress((void**)&wembT_lo, g_wembT_lo);
    cudaGetSymbolAddress((void**)&wih_hi,   g_wih_hi);
    cudaGetSymbolAddress((void**)&wih_lo,   g_wih_lo);
    cudaGetSymbolAddress((void**)&wf_hi,    g_wf_hi);
    cudaGetSymbolAddress((void**)&wf_lo,    g_wf_lo);
    cudaGetSymbolAddress((void**)&whh_hi,   g_whh_hi);
    cudaGetSymbolAddress((void**)&whh_lo,   g_whh_lo);
    cudaGetSymbolAddress((void**)&wout_hi,  g_wout_hi);
    cudaGetSymbolAddress((void**)&wout_lo,  g_wout_lo);
    cudaGetSymbolAddress((void**)&h_hi,     g_h_hi);
    cudaGetSymbolAddress((void**)&h_lo,     g_h_lo);

    cudaFuncSetAttribute(mma_gemm<0, true>,  cudaFuncAttributeMaxDynamicSharedMemorySize, SMEM_BYTES);
    cudaFuncSetAttribute(mma_gemm<0, false>, cudaFuncAttributeMaxDynamicSharedMemorySize, SMEM_BYTES);
    cudaFuncSetAttribute(mma_gemm<1, false>, cudaFuncAttributeMaxDynamicSharedMemorySize, SMEM_BYTES);
    cudaFuncSetAttribute(mma_gemm<2, false>, cudaFuncAttributeMaxDynamicSharedMemorySize, SMEM_BYTES);

    cudaMemsetAsync(h_hi, 0, (size_t)BB * HH * sizeof(__nv_bfloat16), 0);
    cudaMemsetAsync(h_lo, 0, (size_t)BB * HH * sizeof(__nv_bfloat16), 0);

    bfused_kernel<<<(HH + 255) / 256, 256>>>(W_ih, b_emb, b_ih, bfused);

    // input preps
    transpose_split_kernel<<<dim3(VV / 32, EE / 32), dim3(32, 8)>>>(W_emb, wembT_hi, wembT_lo);
    split_kernel<<<512, 256>>>(W_ih, wih_hi, wih_lo, HH * EE / 4);
    split_kernel<<<2048, 256>>>(W_hh, whh_hi, whh_lo, HH * HH / 4);
    split_kernel<<<2048, 256>>>(W_out, wout_hi, wout_lo, OO * HH / 4);
    split_kernel<<<8192, 256>>>(msg, msg_hi, msg_lo, BB * TT * VV / 4);

    // W_fused[H,V] = W_ih @ W_emb -> split bf16 directly (A=[H,E], B=[V,E])
    mma_gemm<2, false><<<dim3(VV / BN, HH / BM), 256, SMEM_BYTES>>>(
        wih_hi, wih_lo, wembT_hi, wembT_lo, nullptr, nullptr,
        nullptr, wf_hi, wf_lo, HH, VV, EE);

    // x_proj[T,B,H] = msg @ W_fused^T + b_fused  (scatter [B*T] -> [T,B])
    mma_gemm<0, true><<<dim3(HH / BN, (BB * TT) / BM), 256, SMEM_BYTES>>>(
        msg_hi, msg_lo, wf_hi, wf_lo, bfused, nullptr,
        xproj, nullptr, nullptr, BB * TT, HH, VV);

    // recurrence: h_{t+1} = tanh(x_t + h_t @ W_hh^T + b_hh)
    __nv_bfloat16* hc_hi = h_hi;
    __nv_bfloat16* hc_lo = h_lo;
    __nv_bfloat16* hn_hi = h_hi + (size_t)BB * HH;
    __nv_bfloat16* hn_lo = h_lo + (size_t)BB * HH;
    for (int t = 0; t < TT; t++) {
        mma_gemm<1, false><<<dim3(HH / BN, BB / BM), 256, SMEM_BYTES>>>(
            hc_hi, hc_lo, whh_hi, whh_lo, b_hh, xproj + (size_t)t * BB * HH,
            nullptr, hn_hi, hn_lo, BB, HH, HH);
        __nv_bfloat16* tmp;
        tmp = hc_hi; hc_hi = hn_hi; hn_hi = tmp;
        tmp = hc_lo; hc_lo = hn_lo; hn_lo = tmp;
    }

    // out = h_T @ W_out^T + b_out
    mma_gemm<0, false><<<dim3(OO / BN, BB / BM), 256, SMEM_BYTES>>>(
        hc_hi, hc_lo, wout_hi, wout_lo, b_out, nullptr,
        out, nullptr, nullptr, BB, OO, HH);
}

// round 5
// speedup vs baseline: 2.8348x; 1.1131x over previous
#include <cuda_runtime.h>
#include <cuda_bf16.h>
#include <cuda_fp16.h>
#include <cstddef>
#include <cstdint>

#define BB   1024
#define TT   32
#define VV   1024
#define EE   512
#define HH   1024
#define OO   1024

// ---------------- device scratch (no runtime allocation) -------------------
__device__ float g_bfused[HH];
__device__ float g_xproj[TT * BB * HH];
__device__ __half g_msg_h[BB * TT * VV];
__device__ __nv_bfloat16 g_wembT_hi[VV * EE];
__device__ __nv_bfloat16 g_wembT_lo[VV * EE];
__device__ __nv_bfloat16 g_wih_hi[HH * EE];
__device__ __nv_bfloat16 g_wih_lo[HH * EE];
__device__ __half g_wf_hi[HH * VV];
__device__ __half g_wf_lo[HH * VV];
__device__ __nv_bfloat16 g_whh_hi[HH * HH];
__device__ __nv_bfloat16 g_whh_lo[HH * HH];
__device__ __nv_bfloat16 g_wout_hi[OO * HH];
__device__ __nv_bfloat16 g_wout_lo[OO * HH];
__device__ __nv_bfloat16 g_h_hi[2][BB * HH];
__device__ __nv_bfloat16 g_h_lo[2][BB * HH];
__device__ unsigned g_bar[2];   // [0]=arrive count, [1]=generation

// ---------------- helpers ---------------------------------------------------
__device__ __forceinline__ void bf16_split(float x, __nv_bfloat16& h, __nv_bfloat16& l) {
    h = __float2bfloat16(x);
    l = __float2bfloat16(x - __bfloat162float(h));
}

__device__ __forceinline__ void ldsm_x4(uint32_t* r, uint32_t addr) {
    asm volatile("ldmatrix.sync.aligned.m8n8.x4.shared.b16 {%0,%1,%2,%3}, [%4];"
                 : "=r"(r[0]), "=r"(r[1]), "=r"(r[2]), "=r"(r[3]) : "r"(addr));
}

__device__ __forceinline__ void mma_bf16(float* d, const uint32_t* a, const uint32_t* b) {
    asm volatile("mma.sync.aligned.m16n8k16.row.col.f32.bf16.bf16.f32 "
                 "{%0,%1,%2,%3}, {%4,%5,%6,%7}, {%8,%9}, {%0,%1,%2,%3};"
                 : "+f"(d[0]), "+f"(d[1]), "+f"(d[2]), "+f"(d[3])
                 : "r"(a[0]), "r"(a[1]), "r"(a[2]), "r"(a[3]),
                   "r"(b[0]), "r"(b[1]));
}

__device__ __forceinline__ void mma_f16(float* d, const uint32_t* a, const uint32_t* b) {
    asm volatile("mma.sync.aligned.m16n8k16.row.col.f32.f16.f16.f32 "
                 "{%0,%1,%2,%3}, {%4,%5,%6,%7}, {%8,%9}, {%0,%1,%2,%3};"
                 : "+f"(d[0]), "+f"(d[1]), "+f"(d[2]), "+f"(d[3])
                 : "r"(a[0]), "r"(a[1]), "r"(a[2]), "r"(a[3]),
                   "r"(b[0]), "r"(b[1]));
}

__device__ __forceinline__ void cp16(uint32_t dst, const void* src) {
    asm volatile("cp.async.cg.shared.global [%0], [%1], 16;" :: "r"(dst), "l"(src));
}
#define CP_COMMIT() asm volatile("cp.async.commit_group;" ::: "memory")
#define CP_WAIT(n)  asm volatile("cp.async.wait_group %0;" :: "n"(n) : "memory")

// ---------------- shared tiling constants -----------------------------------
constexpr int BM = 128, BN = 64, BK = 32, LDT = BK + 8, STAGES = 3;
constexpr int A_ELE = BM * LDT;                 // 5120
constexpr int B_ELE = BN * LDT;                 // 2560
constexpr int STG_ELE = 2 * A_ELE + 2 * B_ELE;  // 15360
constexpr int SMEM_BYTES = STAGES * STG_ELE * 2;        // 92160
constexpr int H_STG_ELE = A_ELE + 2 * B_ELE;    // 10240 (fp16 2-term)
constexpr int H_SMEM_BYTES = STAGES * H_STG_ELE * 2;    // 61440
#define OFF_AHI 0
#define OFF_ALO (A_ELE)
#define OFF_BHI (2 * A_ELE)
#define OFF_BLO (2 * A_ELE + B_ELE)

// ---------------------------------------------------------------------------
// bf16 3-term split GEMM: C[M,N] ~= A[M,K] @ B[N,K]^T (fp32-grade accuracy)
//   EPI 0: Cf = acc + bias (fp32)        EPI 3: acc -> (Chi,Clo) fp16 split
// ---------------------------------------------------------------------------
template <int EPI>
__global__ __launch_bounds__(256)
void mma_gemm(const __nv_bfloat16* __restrict__ Ahi,
              const __nv_bfloat16* __restrict__ Alo,
              const __nv_bfloat16* __restrict__ Bhi,
              const __nv_bfloat16* __restrict__ Blo,
              const float* __restrict__ bias,
              float* __restrict__ Cf,
              void* __restrict__ Chi, void* __restrict__ Clo,
              int M, int N, int K) {
    extern __shared__ __align__(16) __nv_bfloat16 smem[];
    const uint32_t sb = (uint32_t)__cvta_generic_to_shared(smem);
    const int tid = threadIdx.x, lane = tid & 31, wid = tid >> 5;
    const int bm = blockIdx.y * BM, bn = blockIdx.x * BN;
    const int wm = (wid >> 2) * 64, wn = (wid & 3) * 16;
    const int CH = K / BK;

    const int a_r0 = tid >> 2, a_c = (tid & 3) * 8;
    const int a_r1 = (tid + 256) >> 2;
    const int b_r = tid >> 2;

    auto load_chunk = [&](int k0, int s) {
        const uint32_t st = sb + (uint32_t)(s * STG_ELE) * 2;
        const size_t ga0 = (size_t)(bm + a_r0) * K + k0 + a_c;
        const size_t ga1 = (size_t)(bm + a_r1) * K + k0 + a_c;
        const size_t gb  = (size_t)(bn + b_r ) * K + k0 + a_c;
        const uint32_t d0 = (uint32_t)(a_r0 * LDT + a_c) * 2;
        const uint32_t d1 = (uint32_t)(a_r1 * LDT + a_c) * 2;
        const uint32_t db = (uint32_t)(b_r  * LDT + a_c) * 2;
        cp16(st + OFF_AHI * 2 + d0, Ahi + ga0);
        cp16(st + OFF_AHI * 2 + d1, Ahi + ga1);
        cp16(st + OFF_ALO * 2 + d0, Alo + ga0);
        cp16(st + OFF_ALO * 2 + d1, Alo + ga1);
        cp16(st + OFF_BHI * 2 + db, Bhi + gb);
        cp16(st + OFF_BLO * 2 + db, Blo + gb);
    };

    const int a_row = wm + (lane & 7) + ((lane >> 3) & 1) * 8;
    const int a_col = (lane >> 4) * 8;
    const int b_row = wn + (lane >> 4) * 8 + (lane & 7);
    const int b_col = ((lane >> 3) & 1) * 8;
    const uint32_t aoff = (uint32_t)(a_row * LDT + a_col) * 2;
    const uint32_t boff = (uint32_t)(b_row * LDT + b_col) * 2;

    float acc[4][2][4] = {};

    #pragma unroll
    for (int s = 0; s < STAGES - 1; s++) { load_chunk(s * BK, s); CP_COMMIT(); }

    for (int c = 0; c < CH; c++) {
        CP_WAIT(STAGES - 2);
        __syncthreads();
        const int pc = c + STAGES - 1;
        if (pc < CH) load_chunk(pc * BK, pc % STAGES);
        CP_COMMIT();

        const uint32_t st = sb + (uint32_t)((c % STAGES) * STG_ELE) * 2;
        #pragma unroll
        for (int kk = 0; kk < BK; kk += 16) {
            uint32_t ah[4][4], al[4][4], bh[4], bl[4];
            #pragma unroll
            for (int i = 0; i < 4; i++) {
                ldsm_x4(ah[i], st + OFF_AHI * 2 + aoff + (uint32_t)(i * 16 * LDT + kk) * 2);
                ldsm_x4(al[i], st + OFF_ALO * 2 + aoff + (uint32_t)(i * 16 * LDT + kk) * 2);
            }
            ldsm_x4(bh, st + OFF_BHI * 2 + boff + (uint32_t)kk * 2);
            ldsm_x4(bl, st + OFF_BLO * 2 + boff + (uint32_t)kk * 2);
            #pragma unroll
            for (int i = 0; i < 4; i++)
                #pragma unroll
                for (int j = 0; j < 2; j++) {
                    mma_bf16(acc[i][j], ah[i], &bh[j * 2]);
                    mma_bf16(acc[i][j], ah[i], &bl[j * 2]);
                    mma_bf16(acc[i][j], al[i], &bh[j * 2]);
                }
        }
    }

    const int crow = lane >> 2, ccol = (lane & 3) * 2;
    #pragma unroll
    for (int i = 0; i < 4; i++)
        #pragma unroll
        for (int j = 0; j < 2; j++)
            #pragma unroll
            for (int half = 0; half < 2; half++) {
                const int m = bm + wm + i * 16 + crow + half * 8;
                const int n = bn + wn + j * 8 + ccol;
                float v0 = acc[i][j][half * 2 + 0];
                float v1 = acc[i][j][half * 2 + 1];
                if (EPI == 0) {
                    float2 r = { v0 + bias[n], v1 + bias[n + 1] };
                    *reinterpret_cast<float2*>(&Cf[(size_t)m * N + n]) = r;
                } else {  // EPI == 3: fp16 hi/lo split
                    __half h0 = __float2half_rn(v0);
                    __half h1 = __float2half_rn(v1);
                    __half2 hp = { h0, h1 };
                    __half2 lp = { __float2half_rn(v0 - __half2float(h0)),
                                   __float2half_rn(v1 - __half2float(h1)) };
                    *reinterpret_cast<__half2*>((__half*)Chi + (size_t)m * N + n) = hp;
                    *reinterpret_cast<__half2*>((__half*)Clo + (size_t)m * N + n) = lp;
                }
            }
}

// ---------------------------------------------------------------------------
// fp16 2-term GEMM for x_proj: C = A_f16[M,K] @ (Bhi+Blo)[N,K]^T + bias
// scatter: row m -> (m % TT)*BB + m/TT
// ---------------------------------------------------------------------------
__global__ __launch_bounds__(256)
void mma_gemm_h(const __half* __restrict__ A,
                const __half* __restrict__ Bhi,
                const __half* __restrict__ Blo,
                const float* __restrict__ bias,
                float* __restrict__ Cf,
                int M, int N, int K) {
    extern __shared__ __align__(16) __half hsmem[];
    const uint32_t sb = (uint32_t)__cvta_generic_to_shared(hsmem);
    const int tid = threadIdx.x, lane = tid & 31, wid = tid >> 5;
    const int bm = blockIdx.y * BM, bn = blockIdx.x * BN;
    const int wm = (wid >> 2) * 64, wn = (wid & 3) * 16;
    const int CH = K / BK;
    // stage layout: [A (A_ELE)] [Bhi (B_ELE)] [Blo (B_ELE)]
    const int a_r0 = tid >> 2, a_c = (tid & 3) * 8;
    const int a_r1 = (tid + 256) >> 2;
    const int b_r = tid >> 2;

    auto load_chunk = [&](int k0, int s) {
        const uint32_t st = sb + (uint32_t)(s * H_STG_ELE) * 2;
        const size_t ga0 = (size_t)(bm + a_r0) * K + k0 + a_c;
        const size_t ga1 = (size_t)(bm + a_r1) * K + k0 + a_c;
        const size_t gb  = (size_t)(bn + b_r ) * K + k0 + a_c;
        const uint32_t d0 = (uint32_t)(a_r0 * LDT + a_c) * 2;
        const uint32_t d1 = (uint32_t)(a_r1 * LDT + a_c) * 2;
        const uint32_t db = (uint32_t)(b_r  * LDT + a_c) * 2;
        cp16(st + d0, A + ga0);
        cp16(st + d1, A + ga1);
        cp16(st + (uint32_t)A_ELE * 2 + db, Bhi + gb);
        cp16(st + (uint32_t)(A_ELE + B_ELE) * 2 + db, Blo + gb);
    };

    const int a_row = wm + (lane & 7) + ((lane >> 3) & 1) * 8;
    const int a_col = (lane >> 4) * 8;
    const int b_row = wn + (lane >> 4) * 8 + (lane & 7);
    const int b_col = ((lane >> 3) & 1) * 8;
    const uint32_t aoff = (uint32_t)(a_row * LDT + a_col) * 2;
    const uint32_t boff = (uint32_t)(b_row * LDT + b_col) * 2;

    float acc[4][2][4] = {};

    #pragma unroll
    for (int s = 0; s < STAGES - 1; s++) { load_chunk(s * BK, s); CP_COMMIT(); }

    for (int c = 0; c < CH; c++) {
        CP_WAIT(STAGES - 2);
        __syncthreads();
        const int pc = c + STAGES - 1;
        if (pc < CH) load_chunk(pc * BK, pc % STAGES);
        CP_COMMIT();

        const uint32_t st = sb + (uint32_t)((c % STAGES) * H_STG_ELE) * 2;
        #pragma unroll
        for (int kk = 0; kk < BK; kk += 16) {
            uint32_t a4[4][4], bh[4], bl[4];
            #pragma unroll
            for (int i = 0; i < 4; i++)
                ldsm_x4(a4[i], st + aoff + (uint32_t)(i * 16 * LDT + kk) * 2);
            ldsm_x4(bh, st + (uint32_t)A_ELE * 2 + boff + (uint32_t)kk * 2);
            ldsm_x4(bl, st + (uint32_t)(A_ELE + B_ELE) * 2 + boff + (uint32_t)kk * 2);
            #pragma unroll
            for (int i = 0; i < 4; i++)
                #pragma unroll
                for (int j = 0; j < 2; j++) {
                    mma_f16(acc[i][j], a4[i], &bh[j * 2]);
                    mma_f16(acc[i][j], a4[i], &bl[j * 2]);
                }
        }
    }

    const int crow = lane >> 2, ccol = (lane & 3) * 2;
    #pragma unroll
    for (int i = 0; i < 4; i++)
        #pragma unroll
        for (int j = 0; j < 2; j++)
            #pragma unroll
            for (int half = 0; half < 2; half++) {
                const int m = bm + wm + i * 16 + crow + half * 8;
                const int n = bn + wn + j * 8 + ccol;
                const size_t om = (size_t)(m % TT) * BB + (size_t)(m / TT);
                float2 r = { acc[i][j][half * 2 + 0] + bias[n],
                             acc[i][j][half * 2 + 1] + bias[n + 1] };
                *reinterpret_cast<float2*>(&Cf[om * N + n]) = r;
            }
}

// ---------------------------------------------------------------------------
// persistent RNN recurrence: 32 steps in one launch, grid barrier between steps
// grid MUST be (HH/BN=16, BB/BM=8) = 128 CTAs (co-resident at 1 CTA/SM)
// ---------------------------------------------------------------------------
constexpr unsigned NCTAS = (HH / BN) * (BB / BM);   // 128

__device__ __forceinline__ void grid_barrier(unsigned target) {
    __syncthreads();
    if (threadIdx.x == 0) {
        __threadfence();
        unsigned arrived = atomicAdd(&g_bar[0], 1u);
        if (arrived == NCTAS - 1) {
            atomicExch(&g_bar[0], 0u);
            __threadfence();
            atomicAdd(&g_bar[1], 1u);
        } else {
            unsigned g;
            do {
                asm volatile("ld.acquire.gpu.u32 %0, [%1];"
                             : "=r"(g) : "l"(g_bar + 1) : "memory");
            } while (g < target);
        }
        __threadfence();
    }
    __syncthreads();
}

__global__ __launch_bounds__(256)
void rnn_persist(const __nv_bfloat16* __restrict__ Whi,
                 const __nv_bfloat16* __restrict__ Wlo,
                 const float* __restrict__ b_hh,
                 const float* __restrict__ xproj) {
    extern __shared__ __align__(16) __nv_bfloat16 smem[];
    const uint32_t sb = (uint32_t)__cvta_generic_to_shared(smem);
    const int tid = threadIdx.x, lane = tid & 31, wid = tid >> 5;
    const int bm = blockIdx.y * BM, bn = blockIdx.x * BN;
    const int wm = (wid >> 2) * 64, wn = (wid & 3) * 16;
    constexpr int K = HH, CH = K / BK;

    const int a_r0 = tid >> 2, a_c = (tid & 3) * 8;
    const int a_r1 = (tid + 256) >> 2;
    const int b_r = tid >> 2;

    auto load_chunk = [&](const __nv_bfloat16* Ahi, const __nv_bfloat16* Alo,
                          int k0, int s) {
        const uint32_t st = sb + (uint32_t)(s * STG_ELE) * 2;
        const size_t ga0 = (size_t)(bm + a_r0) * K + k0 + a_c;
        const size_t ga1 = (size_t)(bm + a_r1) * K + k0 + a_c;
        const size_t gb  = (size_t)(bn + b_r ) * K + k0 + a_c;
        const uint32_t d0 = (uint32_t)(a_r0 * LDT + a_c) * 2;
        const uint32_t d1 = (uint32_t)(a_r1 * LDT + a_c) * 2;
        const uint32_t db = (uint32_t)(b_r  * LDT + a_c) * 2;
        cp16(st + OFF_AHI * 2 + d0, Ahi + ga0);
        cp16(st + OFF_AHI * 2 + d1, Ahi + ga1);
        cp16(st + OFF_ALO * 2 + d0, Alo + ga0);
        cp16(st + OFF_ALO * 2 + d1, Alo + ga1);
        cp16(st + OFF_BHI * 2 + db, Whi + gb);
        cp16(st + OFF_BLO * 2 + db, Wlo + gb);
    };

    const int a_row = wm + (lane & 7) + ((lane >> 3) & 1) * 8;
    const int a_col = (lane >> 4) * 8;
    const int b_row = wn + (lane >> 4) * 8 + (lane & 7);
    const int b_col = ((lane >> 3) & 1) * 8;
    const uint32_t aoff = (uint32_t)(a_row * LDT + a_col) * 2;
    const uint32_t boff = (uint32_t)(b_row * LDT + b_col) * 2;
    const int crow = lane >> 2, ccol = (lane & 3) * 2;

    for (int t = 0; t < TT; t++) {
        const int cur = t & 1;
        const __nv_bfloat16* Ahi = g_h_hi[cur];
        const __nv_bfloat16* Alo = g_h_lo[cur];
        __nv_bfloat16* Nhi = g_h_hi[cur ^ 1];
        __nv_bfloat16* Nlo = g_h_lo[cur ^ 1];
        const float* xrow = xproj + (size_t)t * BB * HH;

        float acc[4][2][4] = {};

        #pragma unroll
        for (int s = 0; s < STAGES - 1; s++) { load_chunk(Ahi, Alo, s * BK, s); CP_COMMIT(); }

        for (int c = 0; c < CH; c++) {
            CP_WAIT(STAGES - 2);
            __syncthreads();
            const int pc = c + STAGES - 1;
            if (pc < CH) load_chunk(Ahi, Alo, pc * BK, pc % STAGES);
            CP_COMMIT();

            const uint32_t st = sb + (uint32_t)((c % STAGES) * STG_ELE) * 2;
            #pragma unroll
            for (int kk = 0; kk < BK; kk += 16) {
                uint32_t ah[4][4], al[4][4], bh[4], bl[4];
                #pragma unroll
                for (int i = 0; i < 4; i++) {
                    ldsm_x4(ah[i], st + OFF_AHI * 2 + aoff + (uint32_t)(i * 16 * LDT + kk) * 2);
                    ldsm_x4(al[i], st + OFF_ALO * 2 + aoff + (uint32_t)(i * 16 * LDT + kk) * 2);
                }
                ldsm_x4(bh, st + OFF_BHI * 2 + boff + (uint32_t)kk * 2);
                ldsm_x4(bl, st + OFF_BLO * 2 + boff + (uint32_t)kk * 2);
                #pragma unroll
                for (int i = 0; i < 4; i++)
                    #pragma unroll
                    for (int j = 0; j < 2; j++) {
                        mma_bf16(acc[i][j], ah[i], &bh[j * 2]);
                        mma_bf16(acc[i][j], ah[i], &bl[j * 2]);
                        mma_bf16(acc[i][j], al[i], &bh[j * 2]);
                    }
            }
        }

        // epilogue: h_next = tanh(acc + b_hh + xproj[t]) -> bf16 hi/lo
        #pragma unroll
        for (int i = 0; i < 4; i++)
            #pragma unroll
            for (int j = 0; j < 2; j++)
                #pragma unroll
                for (int half = 0; half < 2; half++) {
                    const int m = bm + wm + i * 16 + crow + half * 8;
                    const int n = bn + wn + j * 8 + ccol;
                    const float* ar = xrow + (size_t)m * HH;
                    float v0 = tanhf(acc[i][j][half * 2 + 0] + b_hh[n]     + ar[n]);
                    float v1 = tanhf(acc[i][j][half * 2 + 1] + b_hh[n + 1] + ar[n + 1]);
                    __nv_bfloat162 hp, lp;
                    bf16_split(v0, hp.x, lp.x);
                    bf16_split(v1, hp.y, lp.y);
                    *reinterpret_cast<__nv_bfloat162*>(&Nhi[(size_t)m * HH + n]) = hp;
                    *reinterpret_cast<__nv_bfloat162*>(&Nlo[(size_t)m * HH + n]) = lp;
                }

        if (t + 1 < TT) grid_barrier((unsigned)(t + 1));
    }
}

// ---------------------------------------------------------------------------
// prep kernels
// ---------------------------------------------------------------------------
__global__ void bfused_kernel(const float* __restrict__ W_ih,
                              const float* __restrict__ b_emb,
                              const float* __restrict__ b_ih,
                              float* __restrict__ out) {
    int h = blockIdx.x * blockDim.x + threadIdx.x;
    if (h >= HH) return;
    float s = b_ih[h];
    const float* row = W_ih + (size_t)h * EE;
    #pragma unroll 4
    for (int e = 0; e < EE; e++) s += row[e] * b_emb[e];
    out[h] = s;
}

__global__ void split_kernel(const float* __restrict__ in,
                             __nv_bfloat16* __restrict__ hi,
                             __nv_bfloat16* __restrict__ lo,
                             int n4) {
    int idx = blockIdx.x * blockDim.x + threadIdx.x;
    for (; idx < n4; idx += gridDim.x * blockDim.x) {
        float4 v = reinterpret_cast<const float4*>(in)[idx];
        __nv_bfloat162 hp0, hp1, lp0, lp1;
        bf16_split(v.x, hp0.x, lp0.x);
        bf16_split(v.y, hp0.y, lp0.y);
        bf16_split(v.z, hp1.x, lp1.x);
        bf16_split(v.w, hp1.y, lp1.y);
        reinterpret_cast<__nv_bfloat162*>(hi)[idx * 2 + 0] = hp0;
        reinterpret_cast<__nv_bfloat162*>(hi)[idx * 2 + 1] = hp1;
        reinterpret_cast<__nv_bfloat162*>(lo)[idx * 2 + 0] = lp0;
        reinterpret_cast<__nv_bfloat162*>(lo)[idx * 2 + 1] = lp1;
    }
}

__global__ void cvt_f16_kernel(const float* __restrict__ in,
                               __half* __restrict__ out, int n4) {
    int idx = blockIdx.x * blockDim.x + threadIdx.x;
    for (; idx < n4; idx += gridDim.x * blockDim.x) {
        float4 v = reinterpret_cast<const float4*>(in)[idx];
        __half2 p0 = { __float2half_rn(v.x), __float2half_rn(v.y) };
        __half2 p1 = { __float2half_rn(v.z), __float2half_rn(v.w) };
        reinterpret_cast<__half2*>(out)[idx * 2 + 0] = p0;
        reinterpret_cast<__half2*>(out)[idx * 2 + 1] = p1;
    }
}

__global__ void transpose_split_kernel(const float* __restrict__ in,
                                       __nv_bfloat16* __restrict__ hi,
                                       __nv_bfloat16* __restrict__ lo) {
    __shared__ float t[32][33];
    const int v0 = blockIdx.x * 32, e0 = blockIdx.y * 32;
    for (int i = threadIdx.y; i < 32; i += 8)
        t[i][threadIdx.x] = in[(size_t)(e0 + i) * VV + v0 + threadIdx.x];
    __syncthreads();
    for (int i = threadIdx.y; i < 32; i += 8) {
        float x = t[threadIdx.x][i];
        __nv_bfloat16 h, l;
        bf16_split(x, h, l);
        size_t o = (size_t)(v0 + i) * EE + e0 + threadIdx.x;
        hi[o] = h;
        lo[o] = l;
    }
}

// ---------------------------------------------------------------------------
extern "C" void kernel_launch(void* const* d_in, const int* in_sizes, int n_in,
                              void* d_out, int out_size) {
    const float* msg   = (const float*)d_in[0];
    const float* W_emb = (const float*)d_in[1];
    const float* b_emb = (const float*)d_in[2];
    const float* W_ih  = (const float*)d_in[3];
    const float* b_ih  = (const float*)d_in[4];
    const float* W_hh  = (const float*)d_in[5];
    const float* b_hh  = (const float*)d_in[6];
    const float* W_out = (const float*)d_in[7];
    const float* b_out = (const float*)d_in[8];
    float* out = (float*)d_out;

    float *bfused, *xproj;
    __half *msg_h, *wf_hi, *wf_lo;
    __nv_bfloat16 *wembT_hi, *wembT_lo, *wih_hi, *wih_lo,
                  *whh_hi, *whh_lo, *wout_hi, *wout_lo, *h_hi, *h_lo;
    unsigned* bar;
    cudaGetSymbolAddress((void**)&bfused,   g_bfused);
    cudaGetSymbolAddress((void**)&xproj,    g_xproj);
    cudaGetSymbolAddress((void**)&msg_h,    g_msg_h);
    cudaGetSymbolAddress((void**)&wembT_hi, g_wembT_hi);
    cudaGetSymbolAddress((void**)&wembT_lo, g_wembT_lo);
    cudaGetSymbolAddress((void**)&wih_hi,   g_wih_hi);
    cudaGetSymbolAddress((void**)&wih_lo,   g_wih_lo);
    cudaGetSymbolAddress((void**)&wf_hi,    g_wf_hi);
    cudaGetSymbolAddress((void**)&wf_lo,    g_wf_lo);
    cudaGetSymbolAddress((void**)&whh_hi,   g_whh_hi);
    cudaGetSymbolAddress((void**)&whh_lo,   g_whh_lo);
    cudaGetSymbolAddress((void**)&wout_hi,  g_wout_hi);
    cudaGetSymbolAddress((void**)&wout_lo,  g_wout_lo);
    cudaGetSymbolAddress((void**)&h_hi,     g_h_hi);
    cudaGetSymbolAddress((void**)&h_lo,     g_h_lo);
    cudaGetSymbolAddress((void**)&bar,      g_bar);

    cudaFuncSetAttribute(mma_gemm<0>, cudaFuncAttributeMaxDynamicSharedMemorySize, SMEM_BYTES);
    cudaFuncSetAttribute(mma_gemm<3>, cudaFuncAttributeMaxDynamicSharedMemorySize, SMEM_BYTES);
    cudaFuncSetAttribute(mma_gemm_h,  cudaFuncAttributeMaxDynamicSharedMemorySize, H_SMEM_BYTES);
    cudaFuncSetAttribute(rnn_persist, cudaFuncAttributeMaxDynamicSharedMemorySize, SMEM_BYTES);

    // init: h(0)=0 (buffer 0), barrier state = 0
    cudaMemsetAsync(h_hi, 0, (size_t)BB * HH * sizeof(__nv_bfloat16), 0);
    cudaMemsetAsync(h_lo, 0, (size_t)BB * HH * sizeof(__nv_bfloat16), 0);
    cudaMemsetAsync(bar, 0, 2 * sizeof(unsigned), 0);

    bfused_kernel<<<(HH + 255) / 256, 256>>>(W_ih, b_emb, b_ih, bfused);

    transpose_split_kernel<<<dim3(VV / 32, EE / 32), dim3(32, 8)>>>(W_emb, wembT_hi, wembT_lo);
    split_kernel<<<512, 256>>>(W_ih, wih_hi, wih_lo, HH * EE / 4);
    split_kernel<<<2048, 256>>>(W_hh, whh_hi, whh_lo, HH * HH / 4);
    split_kernel<<<2048, 256>>>(W_out, wout_hi, wout_lo, OO * HH / 4);
    cvt_f16_kernel<<<8192, 256>>>(msg, msg_h, BB * TT * VV / 4);

    // W_fused = W_ih @ W_emb  (bf16 3-term, fp16 hi/lo output)
    mma_gemm<3><<<dim3(VV / BN, HH / BM), 256, SMEM_BYTES>>>(
        wih_hi, wih_lo, wembT_hi, wembT_lo, nullptr,
        nullptr, wf_hi, wf_lo, HH, VV, EE);

    // x_proj = msg @ W_fused^T + b_fused  (fp16 2-term, scatter [B*T]->[T,B])
    mma_gemm_h<<<dim3(HH / BN, (BB * TT) / BM), 256, H_SMEM_BYTES>>>(
        msg_h, wf_hi, wf_lo, bfused, xproj, BB * TT, HH, VV);

    // recurrence: 32 steps, one persistent launch (final h lands in buffer 0)
    rnn_persist<<<dim3(HH / BN, BB / BM), 256, SMEM_BYTES>>>(
        whh_hi, whh_lo, b_hh, xproj);

    // out = h_T @ W_out^T + b_out
    mma_gemm<0><<<dim3(OO / BN, BB / BM), 256, SMEM_BYTES>>>(
        h_hi, h_lo, wout_hi, wout_lo, b_out,
        out, nullptr, nullptr, BB, OO, HH);
}

// round 6
// speedup vs baseline: 4.1150x; 1.4516x over previous
#include <cuda_runtime.h>
#include <cuda_bf16.h>
#include <cuda_fp16.h>
#include <cstddef>
#include <cstdint>

#define BB   1024
#define TT   32
#define VV   1024
#define EE   512
#define HH   1024
#define OO   1024

// ---------------- device scratch (no runtime allocation) -------------------
__device__ float g_bfused[HH];
__device__ float g_xproj[TT * BB * HH];
__device__ __half g_msg_h[BB * TT * VV];
__device__ __nv_bfloat16 g_wembT_hi[VV * EE];
__device__ __nv_bfloat16 g_wembT_lo[VV * EE];
__device__ __nv_bfloat16 g_wih_hi[HH * EE];
__device__ __nv_bfloat16 g_wih_lo[HH * EE];
__device__ __half g_wf[HH * VV];            // W_fused, single fp16
__device__ __half g_whh_hi[HH * HH];
__device__ __half g_whh_lo[HH * HH];
__device__ __half g_wout_hi[OO * HH];
__device__ __half g_wout_lo[OO * HH];
__device__ __half g_h[2][BB * HH];          // hidden state, single fp16
__device__ unsigned g_bar[2];               // [0]=arrive count, [1]=generation

// ---------------- helpers ---------------------------------------------------
__device__ __forceinline__ void bf16_split(float x, __nv_bfloat16& h, __nv_bfloat16& l) {
    h = __float2bfloat16(x);
    l = __float2bfloat16(x - __bfloat162float(h));
}
__device__ __forceinline__ void f16_split(float x, __half& h, __half& l) {
    h = __float2half_rn(x);
    l = __float2half_rn(x - __half2float(h));
}

__device__ __forceinline__ void ldsm_x4(uint32_t* r, uint32_t addr) {
    asm volatile("ldmatrix.sync.aligned.m8n8.x4.shared.b16 {%0,%1,%2,%3}, [%4];"
                 : "=r"(r[0]), "=r"(r[1]), "=r"(r[2]), "=r"(r[3]) : "r"(addr));
}

__device__ __forceinline__ void mma_bf16(float* d, const uint32_t* a, const uint32_t* b) {
    asm volatile("mma.sync.aligned.m16n8k16.row.col.f32.bf16.bf16.f32 "
                 "{%0,%1,%2,%3}, {%4,%5,%6,%7}, {%8,%9}, {%0,%1,%2,%3};"
                 : "+f"(d[0]), "+f"(d[1]), "+f"(d[2]), "+f"(d[3])
                 : "r"(a[0]), "r"(a[1]), "r"(a[2]), "r"(a[3]),
                   "r"(b[0]), "r"(b[1]));
}

__device__ __forceinline__ void mma_f16(float* d, const uint32_t* a, const uint32_t* b) {
    asm volatile("mma.sync.aligned.m16n8k16.row.col.f32.f16.f16.f32 "
                 "{%0,%1,%2,%3}, {%4,%5,%6,%7}, {%8,%9}, {%0,%1,%2,%3};"
                 : "+f"(d[0]), "+f"(d[1]), "+f"(d[2]), "+f"(d[3])
                 : "r"(a[0]), "r"(a[1]), "r"(a[2]), "r"(a[3]),
                   "r"(b[0]), "r"(b[1]));
}

__device__ __forceinline__ void cp16(uint32_t dst, const void* src) {
    asm volatile("cp.async.cg.shared.global [%0], [%1], 16;" :: "r"(dst), "l"(src));
}
#define CP_COMMIT() asm volatile("cp.async.commit_group;" ::: "memory")
#define CP_WAIT(n)  asm volatile("cp.async.wait_group %0;" :: "n"(n) : "memory")

// ---------------- tiling constants ------------------------------------------
constexpr int BM = 128, BN = 64, BK = 32, LDT = BK + 8, STAGES = 3;
constexpr int A_ELE = BM * LDT;                 // 5120
constexpr int B_ELE = BN * LDT;                 // 2560
constexpr int BF3_STG = 2 * A_ELE + 2 * B_ELE;  // bf16 3-term stage
constexpr int BF3_SMEM = STAGES * BF3_STG * 2;  // 92160
#define OFF_AHI 0
#define OFF_ALO (A_ELE)
#define OFF_BHI (2 * A_ELE)
#define OFF_BLO (2 * A_ELE + B_ELE)

// ---------------------------------------------------------------------------
// bf16 3-term GEMM (used ONLY for W_fused = W_ih @ W_emb, output single fp16)
// ---------------------------------------------------------------------------
__global__ __launch_bounds__(256)
void mma_gemm_bf3(const __nv_bfloat16* __restrict__ Ahi,
                  const __nv_bfloat16* __restrict__ Alo,
                  const __nv_bfloat16* __restrict__ Bhi,
                  const __nv_bfloat16* __restrict__ Blo,
                  __half* __restrict__ Cout,
                  int M, int N, int K) {
    extern __shared__ __align__(16) __nv_bfloat16 smem[];
    const uint32_t sb = (uint32_t)__cvta_generic_to_shared(smem);
    const int tid = threadIdx.x, lane = tid & 31, wid = tid >> 5;
    const int bm = blockIdx.y * BM, bn = blockIdx.x * BN;
    const int wm = (wid >> 2) * 64, wn = (wid & 3) * 16;
    const int CH = K / BK;

    const int a_r0 = tid >> 2, a_c = (tid & 3) * 8;
    const int a_r1 = (tid + 256) >> 2;
    const int b_r = tid >> 2;

    auto load_chunk = [&](int k0, int s) {
        const uint32_t st = sb + (uint32_t)(s * BF3_STG) * 2;
        const size_t ga0 = (size_t)(bm + a_r0) * K + k0 + a_c;
        const size_t ga1 = (size_t)(bm + a_r1) * K + k0 + a_c;
        const size_t gb  = (size_t)(bn + b_r ) * K + k0 + a_c;
        const uint32_t d0 = (uint32_t)(a_r0 * LDT + a_c) * 2;
        const uint32_t d1 = (uint32_t)(a_r1 * LDT + a_c) * 2;
        const uint32_t db = (uint32_t)(b_r  * LDT + a_c) * 2;
        cp16(st + OFF_AHI * 2 + d0, Ahi + ga0);
        cp16(st + OFF_AHI * 2 + d1, Ahi + ga1);
        cp16(st + OFF_ALO * 2 + d0, Alo + ga0);
        cp16(st + OFF_ALO * 2 + d1, Alo + ga1);
        cp16(st + OFF_BHI * 2 + db, Bhi + gb);
        cp16(st + OFF_BLO * 2 + db, Blo + gb);
    };

    const int a_row = wm + (lane & 7) + ((lane >> 3) & 1) * 8;
    const int a_col = (lane >> 4) * 8;
    const int b_row = wn + (lane >> 4) * 8 + (lane & 7);
    const int b_col = ((lane >> 3) & 1) * 8;
    const uint32_t aoff = (uint32_t)(a_row * LDT + a_col) * 2;
    const uint32_t boff = (uint32_t)(b_row * LDT + b_col) * 2;

    float acc[4][2][4] = {};

    #pragma unroll
    for (int s = 0; s < STAGES - 1; s++) { load_chunk(s * BK, s); CP_COMMIT(); }

    for (int c = 0; c < CH; c++) {
        CP_WAIT(STAGES - 2);
        __syncthreads();
        const int pc = c + STAGES - 1;
        if (pc < CH) load_chunk(pc * BK, pc % STAGES);
        CP_COMMIT();

        const uint32_t st = sb + (uint32_t)((c % STAGES) * BF3_STG) * 2;
        #pragma unroll
        for (int kk = 0; kk < BK; kk += 16) {
            uint32_t ah[4][4], al[4][4], bh[4], bl[4];
            #pragma unroll
            for (int i = 0; i < 4; i++) {
                ldsm_x4(ah[i], st + OFF_AHI * 2 + aoff + (uint32_t)(i * 16 * LDT + kk) * 2);
                ldsm_x4(al[i], st + OFF_ALO * 2 + aoff + (uint32_t)(i * 16 * LDT + kk) * 2);
            }
            ldsm_x4(bh, st + OFF_BHI * 2 + boff + (uint32_t)kk * 2);
            ldsm_x4(bl, st + OFF_BLO * 2 + boff + (uint32_t)kk * 2);
            #pragma unroll
            for (int i = 0; i < 4; i++)
                #pragma unroll
                for (int j = 0; j < 2; j++) {
                    mma_bf16(acc[i][j], ah[i], &bh[j * 2]);
                    mma_bf16(acc[i][j], ah[i], &bl[j * 2]);
                    mma_bf16(acc[i][j], al[i], &bh[j * 2]);
                }
        }
    }

    const int crow = lane >> 2, ccol = (lane & 3) * 2;
    #pragma unroll
    for (int i = 0; i < 4; i++)
        #pragma unroll
        for (int j = 0; j < 2; j++)
            #pragma unroll
            for (int half = 0; half < 2; half++) {
                const int m = bm + wm + i * 16 + crow + half * 8;
                const int n = bn + wn + j * 8 + ccol;
                __half2 hp = { __float2half_rn(acc[i][j][half * 2 + 0]),
                               __float2half_rn(acc[i][j][half * 2 + 1]) };
                *reinterpret_cast<__half2*>(&Cout[(size_t)m * N + n]) = hp;
            }
}

// ---------------------------------------------------------------------------
// fp16 GEMM, NB = number of B planes (1 or 2):
//   Cf[M,N] = A[M,K] @ (Bhi (+Blo))[N,K]^T + bias   (fp32 out)
//   SCATTER: row m -> (m % TT)*BB + m/TT
// ---------------------------------------------------------------------------
template <int NB, bool SCATTER>
__global__ __launch_bounds__(256)
void mma_gemm_h(const __half* __restrict__ A,
                const __half* __restrict__ Bhi,
                const __half* __restrict__ Blo,
                const float* __restrict__ bias,
                float* __restrict__ Cf,
                int M, int N, int K) {
    constexpr int STG = A_ELE + NB * B_ELE;
    extern __shared__ __align__(16) __half hsmem[];
    const uint32_t sb = (uint32_t)__cvta_generic_to_shared(hsmem);
    const int tid = threadIdx.x, lane = tid & 31, wid = tid >> 5;
    const int bm = blockIdx.y * BM, bn = blockIdx.x * BN;
    const int wm = (wid >> 2) * 64, wn = (wid & 3) * 16;
    const int CH = K / BK;

    const int a_r0 = tid >> 2, a_c = (tid & 3) * 8;
    const int a_r1 = (tid + 256) >> 2;
    const int b_r = tid >> 2;

    auto load_chunk = [&](int k0, int s) {
        const uint32_t st = sb + (uint32_t)(s * STG) * 2;
        const size_t ga0 = (size_t)(bm + a_r0) * K + k0 + a_c;
        const size_t ga1 = (size_t)(bm + a_r1) * K + k0 + a_c;
        const size_t gb  = (size_t)(bn + b_r ) * K + k0 + a_c;
        const uint32_t d0 = (uint32_t)(a_r0 * LDT + a_c) * 2;
        const uint32_t d1 = (uint32_t)(a_r1 * LDT + a_c) * 2;
        const uint32_t db = (uint32_t)(b_r  * LDT + a_c) * 2;
        cp16(st + d0, A + ga0);
        cp16(st + d1, A + ga1);
        cp16(st + (uint32_t)A_ELE * 2 + db, Bhi + gb);
        if (NB == 2)
            cp16(st + (uint32_t)(A_ELE + B_ELE) * 2 + db, Blo + gb);
    };

    const int a_row = wm + (lane & 7) + ((lane >> 3) & 1) * 8;
    const int a_col = (lane >> 4) * 8;
    const int b_row = wn + (lane >> 4) * 8 + (lane & 7);
    const int b_col = ((lane >> 3) & 1) * 8;
    const uint32_t aoff = (uint32_t)(a_row * LDT + a_col) * 2;
    const uint32_t boff = (uint32_t)(b_row * LDT + b_col) * 2;

    float acc[4][2][4] = {};

    #pragma unroll
    for (int s = 0; s < STAGES - 1; s++) { load_chunk(s * BK, s); CP_COMMIT(); }

    for (int c = 0; c < CH; c++) {
        CP_WAIT(STAGES - 2);
        __syncthreads();
        const int pc = c + STAGES - 1;
        if (pc < CH) load_chunk(pc * BK, pc % STAGES);
        CP_COMMIT();

        const uint32_t st = sb + (uint32_t)((c % STAGES) * STG) * 2;
        #pragma unroll
        for (int kk = 0; kk < BK; kk += 16) {
            uint32_t a4[4][4], bh[4], bl[4];
            #pragma unroll
            for (int i = 0; i < 4; i++)
                ldsm_x4(a4[i], st + aoff + (uint32_t)(i * 16 * LDT + kk) * 2);
            ldsm_x4(bh, st + (uint32_t)A_ELE * 2 + boff + (uint32_t)kk * 2);
            if (NB == 2)
                ldsm_x4(bl, st + (uint32_t)(A_ELE + B_ELE) * 2 + boff + (uint32_t)kk * 2);
            #pragma unroll
            for (int i = 0; i < 4; i++)
                #pragma unroll
                for (int j = 0; j < 2; j++) {
                    mma_f16(acc[i][j], a4[i], &bh[j * 2]);
                    if (NB == 2) mma_f16(acc[i][j], a4[i], &bl[j * 2]);
                }
        }
    }

    const int crow = lane >> 2, ccol = (lane & 3) * 2;
    #pragma unroll
    for (int i = 0; i < 4; i++)
        #pragma unroll
        for (int j = 0; j < 2; j++)
            #pragma unroll
            for (int half = 0; half < 2; half++) {
                const int m = bm + wm + i * 16 + crow + half * 8;
                const int n = bn + wn + j * 8 + ccol;
                size_t om = (size_t)m;
                if (SCATTER) om = (size_t)(m % TT) * BB + (size_t)(m / TT);
                float2 r = { acc[i][j][half * 2 + 0] + bias[n],
                             acc[i][j][half * 2 + 1] + bias[n + 1] };
                *reinterpret_cast<float2*>(&Cf[om * N + n]) = r;
            }
}

// ---------------------------------------------------------------------------
// persistent RNN recurrence: fp16 h (single plane), W_hh fp16 hi+lo (2-term)
// grid MUST be (HH/BN=16, BB/BM=8) = 128 CTAs (co-resident, 1/SM)
// ---------------------------------------------------------------------------
constexpr unsigned NCTAS = (HH / BN) * (BB / BM);   // 128
constexpr int RNN_STG = A_ELE + 2 * B_ELE;          // 10240 elems
constexpr int RNN_SMEM = STAGES * RNN_STG * 2;      // 61440 B

__device__ __forceinline__ void grid_barrier(unsigned target) {
    __syncthreads();
    if (threadIdx.x == 0) {
        __threadfence();
        unsigned arrived = atomicAdd(&g_bar[0], 1u);
        if (arrived == NCTAS - 1) {
            atomicExch(&g_bar[0], 0u);
            __threadfence();
            atomicAdd(&g_bar[1], 1u);
        } else {
            unsigned g;
            do {
                asm volatile("ld.acquire.gpu.u32 %0, [%1];"
                             : "=r"(g) : "l"(g_bar + 1) : "memory");
            } while (g < target);
        }
        __threadfence();
    }
    __syncthreads();
}

__global__ __launch_bounds__(256)
void rnn_persist(const __half* __restrict__ Whi,
                 const __half* __restrict__ Wlo,
                 const float* __restrict__ b_hh,
                 const float* __restrict__ xproj) {
    extern __shared__ __align__(16) __half hsmem[];
    const uint32_t sb = (uint32_t)__cvta_generic_to_shared(hsmem);
    const int tid = threadIdx.x, lane = tid & 31, wid = tid >> 5;
    const int bm = blockIdx.y * BM, bn = blockIdx.x * BN;
    const int wm = (wid >> 2) * 64, wn = (wid & 3) * 16;
    constexpr int K = HH, CH = K / BK;

    const int a_r0 = tid >> 2, a_c = (tid & 3) * 8;
    const int a_r1 = (tid + 256) >> 2;
    const int b_r = tid >> 2;

    auto load_chunk = [&](const __half* A, int k0, int s) {
        const uint32_t st = sb + (uint32_t)(s * RNN_STG) * 2;
        const size_t ga0 = (size_t)(bm + a_r0) * K + k0 + a_c;
        const size_t ga1 = (size_t)(bm + a_r1) * K + k0 + a_c;
        const size_t gb  = (size_t)(bn + b_r ) * K + k0 + a_c;
        const uint32_t d0 = (uint32_t)(a_r0 * LDT + a_c) * 2;
        const uint32_t d1 = (uint32_t)(a_r1 * LDT + a_c) * 2;
        const uint32_t db = (uint32_t)(b_r  * LDT + a_c) * 2;
        cp16(st + d0, A + ga0);
        cp16(st + d1, A + ga1);
        cp16(st + (uint32_t)A_ELE * 2 + db, Whi + gb);
        cp16(st + (uint32_t)(A_ELE + B_ELE) * 2 + db, Wlo + gb);
    };

    const int a_row = wm + (lane & 7) + ((lane >> 3) & 1) * 8;
    const int a_col = (lane >> 4) * 8;
    const int b_row = wn + (lane >> 4) * 8 + (lane & 7);
    const int b_col = ((lane >> 3) & 1) * 8;
    const uint32_t aoff = (uint32_t)(a_row * LDT + a_col) * 2;
    const uint32_t boff = (uint32_t)(b_row * LDT + b_col) * 2;
    const int crow = lane >> 2, ccol = (lane & 3) * 2;

    for (int t = 0; t < TT; t++) {
        const int cur = t & 1;
        const __half* Acur = g_h[cur];
        __half* Nxt = g_h[cur ^ 1];
        const float* xrow = xproj + (size_t)t * BB * HH;

        float acc[4][2][4] = {};

        #pragma unroll
        for (int s = 0; s < STAGES - 1; s++) { load_chunk(Acur, s * BK, s); CP_COMMIT(); }

        for (int c = 0; c < CH; c++) {
            CP_WAIT(STAGES - 2);
            __syncthreads();
            const int pc = c + STAGES - 1;
            if (pc < CH) load_chunk(Acur, pc * BK, pc % STAGES);
            CP_COMMIT();

            const uint32_t st = sb + (uint32_t)((c % STAGES) * RNN_STG) * 2;
            #pragma unroll
            for (int kk = 0; kk < BK; kk += 16) {
                uint32_t a4[4][4], bh[4], bl[4];
                #pragma unroll
                for (int i = 0; i < 4; i++)
                    ldsm_x4(a4[i], st + aoff + (uint32_t)(i * 16 * LDT + kk) * 2);
                ldsm_x4(bh, st + (uint32_t)A_ELE * 2 + boff + (uint32_t)kk * 2);
                ldsm_x4(bl, st + (uint32_t)(A_ELE + B_ELE) * 2 + boff + (uint32_t)kk * 2);
                #pragma unroll
                for (int i = 0; i < 4; i++)
                    #pragma unroll
                    for (int j = 0; j < 2; j++) {
                        mma_f16(acc[i][j], a4[i], &bh[j * 2]);
                        mma_f16(acc[i][j], a4[i], &bl[j * 2]);
                    }
            }
        }

        // epilogue: h_next = tanh(acc + b_hh + xproj[t]) -> single fp16
        #pragma unroll
        for (int i = 0; i < 4; i++)
            #pragma unroll
            for (int j = 0; j < 2; j++)
                #pragma unroll
                for (int half = 0; half < 2; half++) {
                    const int m = bm + wm + i * 16 + crow + half * 8;
                    const int n = bn + wn + j * 8 + ccol;
                    const float* ar = xrow + (size_t)m * HH;
                    float v0 = tanhf(acc[i][j][half * 2 + 0] + b_hh[n]     + ar[n]);
                    float v1 = tanhf(acc[i][j][half * 2 + 1] + b_hh[n + 1] + ar[n + 1]);
                    __half2 hp = { __float2half_rn(v0), __float2half_rn(v1) };
                    *reinterpret_cast<__half2*>(&Nxt[(size_t)m * HH + n]) = hp;
                }

        if (t + 1 < TT) grid_barrier((unsigned)(t + 1));
    }
}

// ---------------------------------------------------------------------------
// prep kernels
// ---------------------------------------------------------------------------
__global__ void bfused_kernel(const float* __restrict__ W_ih,
                              const float* __restrict__ b_emb,
                              const float* __restrict__ b_ih,
                              float* __restrict__ out) {
    int h = blockIdx.x * blockDim.x + threadIdx.x;
    if (h >= HH) return;
    float s = b_ih[h];
    const float* row = W_ih + (size_t)h * EE;
    #pragma unroll 4
    for (int e = 0; e < EE; e++) s += row[e] * b_emb[e];
    out[h] = s;
}

__global__ void split_bf16_kernel(const float* __restrict__ in,
                                  __nv_bfloat16* __restrict__ hi,
                                  __nv_bfloat16* __restrict__ lo,
                                  int n4) {
    int idx = blockIdx.x * blockDim.x + threadIdx.x;
    for (; idx < n4; idx += gridDim.x * blockDim.x) {
        float4 v = reinterpret_cast<const float4*>(in)[idx];
        __nv_bfloat162 hp0, hp1, lp0, lp1;
        bf16_split(v.x, hp0.x, lp0.x);
        bf16_split(v.y, hp0.y, lp0.y);
        bf16_split(v.z, hp1.x, lp1.x);
        bf16_split(v.w, hp1.y, lp1.y);
        reinterpret_cast<__nv_bfloat162*>(hi)[idx * 2 + 0] = hp0;
        reinterpret_cast<__nv_bfloat162*>(hi)[idx * 2 + 1] = hp1;
        reinterpret_cast<__nv_bfloat162*>(lo)[idx * 2 + 0] = lp0;
        reinterpret_cast<__nv_bfloat162*>(lo)[idx * 2 + 1] = lp1;
    }
}

__global__ void split_f16_kernel(const float* __restrict__ in,
                                 __half* __restrict__ hi,
                                 __half* __restrict__ lo,
                                 int n4) {
    int idx = blockIdx.x * blockDim.x + threadIdx.x;
    for (; idx < n4; idx += gridDim.x * blockDim.x) {
        float4 v = reinterpret_cast<const float4*>(in)[idx];
        __half2 hp0, hp1, lp0, lp1;
        f16_split(v.x, hp0.x, lp0.x);
        f16_split(v.y, hp0.y, lp0.y);
        f16_split(v.z, hp1.x, lp1.x);
        f16_split(v.w, hp1.y, lp1.y);
        reinterpret_cast<__half2*>(hi)[idx * 2 + 0] = hp0;
        reinterpret_cast<__half2*>(hi)[idx * 2 + 1] = hp1;
        reinterpret_cast<__half2*>(lo)[idx * 2 + 0] = lp0;
        reinterpret_cast<__half2*>(lo)[idx * 2 + 1] = lp1;
    }
}

__global__ void cvt_f16_kernel(const float* __restrict__ in,
                               __half* __restrict__ out, int n4) {
    int idx = blockIdx.x * blockDim.x + threadIdx.x;
    for (; idx < n4; idx += gridDim.x * blockDim.x) {
        float4 v = reinterpret_cast<const float4*>(in)[idx];
        __half2 p0 = { __float2half_rn(v.x), __float2half_rn(v.y) };
        __half2 p1 = { __float2half_rn(v.z), __float2half_rn(v.w) };
        reinterpret_cast<__half2*>(out)[idx * 2 + 0] = p0;
        reinterpret_cast<__half2*>(out)[idx * 2 + 1] = p1;
    }
}

__global__ void transpose_split_kernel(const float* __restrict__ in,
                                       __nv_bfloat16* __restrict__ hi,
                                       __nv_bfloat16* __restrict__ lo) {
    __shared__ float t[32][33];
    const int v0 = blockIdx.x * 32, e0 = blockIdx.y * 32;
    for (int i = threadIdx.y; i < 32; i += 8)
        t[i][threadIdx.x] = in[(size_t)(e0 + i) * VV + v0 + threadIdx.x];
    __syncthreads();
    for (int i = threadIdx.y; i < 32; i += 8) {
        float x = t[threadIdx.x][i];
        __nv_bfloat16 h, l;
        bf16_split(x, h, l);
        size_t o = (size_t)(v0 + i) * EE + e0 + threadIdx.x;
        hi[o] = h;
        lo[o] = l;
    }
}

// ---------------------------------------------------------------------------
extern "C" void kernel_launch(void* const* d_in, const int* in_sizes, int n_in,
                              void* d_out, int out_size) {
    const float* msg   = (const float*)d_in[0];
    const float* W_emb = (const float*)d_in[1];
    const float* b_emb = (const float*)d_in[2];
    const float* W_ih  = (const float*)d_in[3];
    const float* b_ih  = (const float*)d_in[4];
    const float* W_hh  = (const float*)d_in[5];
    const float* b_hh  = (const float*)d_in[6];
    const float* W_out = (const float*)d_in[7];
    const float* b_out = (const float*)d_in[8];
    float* out = (float*)d_out;

    float *bfused, *xproj;
    __half *msg_h, *wf, *whh_hi, *whh_lo, *wout_hi, *wout_lo, *hbuf;
    __nv_bfloat16 *wembT_hi, *wembT_lo, *wih_hi, *wih_lo;
    unsigned* bar;
    cudaGetSymbolAddress((void**)&bfused,   g_bfused);
    cudaGetSymbolAddress((void**)&xproj,    g_xproj);
    cudaGetSymbolAddress((void**)&msg_h,    g_msg_h);
    cudaGetSymbolAddress((void**)&wembT_hi, g_wembT_hi);
    cudaGetSymbolAddress((void**)&wembT_lo, g_wembT_lo);
    cudaGetSymbolAddress((void**)&wih_hi,   g_wih_hi);
    cudaGetSymbolAddress((void**)&wih_lo,   g_wih_lo);
    cudaGetSymbolAddress((void**)&wf,       g_wf);
    cudaGetSymbolAddress((void**)&whh_hi,   g_whh_hi);
    cudaGetSymbolAddress((void**)&whh_lo,   g_whh_lo);
    cudaGetSymbolAddress((void**)&wout_hi,  g_wout_hi);
    cudaGetSymbolAddress((void**)&wout_lo,  g_wout_lo);
    cudaGetSymbolAddress((void**)&hbuf,     g_h);
    cudaGetSymbolAddress((void**)&bar,      g_bar);

    cudaFuncSetAttribute(mma_gemm_bf3, cudaFuncAttributeMaxDynamicSharedMemorySize, BF3_SMEM);
    cudaFuncSetAttribute(mma_gemm_h<1, true>,
                         cudaFuncAttributeMaxDynamicSharedMemorySize,
                         STAGES * (A_ELE + B_ELE) * 2);
    cudaFuncSetAttribute(mma_gemm_h<2, false>,
                         cudaFuncAttributeMaxDynamicSharedMemorySize,
                         STAGES * (A_ELE + 2 * B_ELE) * 2);
    cudaFuncSetAttribute(rnn_persist, cudaFuncAttributeMaxDynamicSharedMemorySize, RNN_SMEM);

    // init: h(0)=0 (buffer 0), barrier state = 0
    cudaMemsetAsync(hbuf, 0, (size_t)BB * HH * sizeof(__half), 0);
    cudaMemsetAsync(bar, 0, 2 * sizeof(unsigned), 0);

    bfused_kernel<<<(HH + 255) / 256, 256>>>(W_ih, b_emb, b_ih, bfused);

    transpose_split_kernel<<<dim3(VV / 32, EE / 32), dim3(32, 8)>>>(W_emb, wembT_hi, wembT_lo);
    split_bf16_kernel<<<512, 256>>>(W_ih, wih_hi, wih_lo, HH * EE / 4);
    split_f16_kernel<<<2048, 256>>>(W_hh, whh_hi, whh_lo, HH * HH / 4);
    split_f16_kernel<<<2048, 256>>>(W_out, wout_hi, wout_lo, OO * HH / 4);
    cvt_f16_kernel<<<8192, 256>>>(msg, msg_h, BB * TT * VV / 4);

    // W_fused = W_ih @ W_emb  (bf16 3-term, single fp16 output)
    mma_gemm_bf3<<<dim3(VV / BN, HH / BM), 256, BF3_SMEM>>>(
        wih_hi, wih_lo, wembT_hi, wembT_lo, wf, HH, VV, EE);

    // x_proj = msg @ W_fused^T + b_fused  (fp16 1-term, scatter [B*T]->[T,B])
    mma_gemm_h<1, true><<<dim3(HH / BN, (BB * TT) / BM), 256,
                          STAGES * (A_ELE + B_ELE) * 2>>>(
        msg_h, wf, nullptr, bfused, xproj, BB * TT, HH, VV);

    // recurrence: 32 steps, one persistent launch (final h -> buffer 0)
    rnn_persist<<<dim3(HH / BN, BB / BM), 256, RNN_SMEM>>>(
        whh_hi, whh_lo, b_hh, xproj);

    // out = h_T @ W_out^T + b_out  (fp16 2-term)
    mma_gemm_h<2, false><<<dim3(OO / BN, BB / BM), 256,
                           STAGES * (A_ELE + 2 * B_ELE) * 2>>>(
        hbuf, wout_hi, wout_lo, b_out, out, BB, OO, HH);
}

// round 8
// speedup vs baseline: 4.8153x; 1.1702x over previous
#include <cuda_runtime.h>
#include <cuda_bf16.h>
#include <cuda_fp16.h>
#include <cstddef>
#include <cstdint>

#define BB   1024
#define TT   32
#define VV   1024
#define EE   512
#define HH   1024
#define OO   1024

// ---------------- device scratch (no runtime allocation) -------------------
__device__ float g_bfused[HH];
__device__ float g_xproj[TT * BB * HH];
__device__ __half g_msg_h[BB * TT * VV];
__device__ __nv_bfloat16 g_wembT_hi[VV * EE];
__device__ __nv_bfloat16 g_wembT_lo[VV * EE];
__device__ __nv_bfloat16 g_wih_hi[HH * EE];
__device__ __nv_bfloat16 g_wih_lo[HH * EE];
__device__ __half g_wf[HH * VV];            // W_fused, single fp16
__device__ __half g_whh[HH * HH];           // W_hh, single fp16
__device__ __half g_wout_hi[OO * HH];
__device__ __half g_wout_lo[OO * HH];
__device__ __half g_h[2][BB * HH];          // hidden state, single fp16
__device__ unsigned g_bar[2];               // [0]=arrive count, [1]=generation

// ---------------- helpers ---------------------------------------------------
__device__ __forceinline__ void bf16_split(float x, __nv_bfloat16& h, __nv_bfloat16& l) {
    h = __float2bfloat16(x);
    l = __float2bfloat16(x - __bfloat162float(h));
}
__device__ __forceinline__ void f16_split(float x, __half& h, __half& l) {
    h = __float2half_rn(x);
    l = __float2half_rn(x - __half2float(h));
}

__device__ __forceinline__ void ldsm_x4(uint32_t* r, uint32_t addr) {
    asm volatile("ldmatrix.sync.aligned.m8n8.x4.shared.b16 {%0,%1,%2,%3}, [%4];"
                 : "=r"(r[0]), "=r"(r[1]), "=r"(r[2]), "=r"(r[3]) : "r"(addr));
}

__device__ __forceinline__ void mma_bf16(float* d, const uint32_t* a, const uint32_t* b) {
    asm volatile("mma.sync.aligned.m16n8k16.row.col.f32.bf16.bf16.f32 "
                 "{%0,%1,%2,%3}, {%4,%5,%6,%7}, {%8,%9}, {%0,%1,%2,%3};"
                 : "+f"(d[0]), "+f"(d[1]), "+f"(d[2]), "+f"(d[3])
                 : "r"(a[0]), "r"(a[1]), "r"(a[2]), "r"(a[3]),
                   "r"(b[0]), "r"(b[1]));
}

__device__ __forceinline__ void mma_f16(float* d, const uint32_t* a, const uint32_t* b) {
    asm volatile("mma.sync.aligned.m16n8k16.row.col.f32.f16.f16.f32 "
                 "{%0,%1,%2,%3}, {%4,%5,%6,%7}, {%8,%9}, {%0,%1,%2,%3};"
                 : "+f"(d[0]), "+f"(d[1]), "+f"(d[2]), "+f"(d[3])
                 : "r"(a[0]), "r"(a[1]), "r"(a[2]), "r"(a[3]),
                   "r"(b[0]), "r"(b[1]));
}

__device__ __forceinline__ void cp16(uint32_t dst, const void* src) {
    asm volatile("cp.async.cg.shared.global [%0], [%1], 16;" :: "r"(dst), "l"(src));
}
#define CP_COMMIT() asm volatile("cp.async.commit_group;" ::: "memory")
#define CP_WAIT(n)  asm volatile("cp.async.wait_group %0;" :: "n"(n) : "memory")

// ---------------- tiling constants (non-persistent GEMMs) -------------------
constexpr int BM = 128, BN = 64, BK = 32, LDT = BK + 8, STAGES = 3;
constexpr int A_ELE = BM * LDT;                 // 5120
constexpr int B_ELE = BN * LDT;                 // 2560
constexpr int BF3_STG = 2 * A_ELE + 2 * B_ELE;
constexpr int BF3_SMEM = STAGES * BF3_STG * 2;
#define OFF_AHI 0
#define OFF_ALO (A_ELE)
#define OFF_BHI (2 * A_ELE)
#define OFF_BLO (2 * A_ELE + B_ELE)

// ---------------------------------------------------------------------------
// bf16 3-term GEMM (only for W_fused = W_ih @ W_emb, output single fp16)
// ---------------------------------------------------------------------------
__global__ __launch_bounds__(256)
void mma_gemm_bf3(const __nv_bfloat16* __restrict__ Ahi,
                  const __nv_bfloat16* __restrict__ Alo,
                  const __nv_bfloat16* __restrict__ Bhi,
                  const __nv_bfloat16* __restrict__ Blo,
                  __half* __restrict__ Cout,
                  int M, int N, int K) {
    extern __shared__ __align__(16) __nv_bfloat16 smem[];
    const uint32_t sb = (uint32_t)__cvta_generic_to_shared(smem);
    const int tid = threadIdx.x, lane = tid & 31, wid = tid >> 5;
    const int bm = blockIdx.y * BM, bn = blockIdx.x * BN;
    const int wm = (wid >> 2) * 64, wn = (wid & 3) * 16;
    const int CH = K / BK;

    const int a_r0 = tid >> 2, a_c = (tid & 3) * 8;
    const int a_r1 = (tid + 256) >> 2;
    const int b_r = tid >> 2;

    auto load_chunk = [&](int k0, int s) {
        const uint32_t st = sb + (uint32_t)(s * BF3_STG) * 2;
        const size_t ga0 = (size_t)(bm + a_r0) * K + k0 + a_c;
        const size_t ga1 = (size_t)(bm + a_r1) * K + k0 + a_c;
        const size_t gb  = (size_t)(bn + b_r ) * K + k0 + a_c;
        const uint32_t d0 = (uint32_t)(a_r0 * LDT + a_c) * 2;
        const uint32_t d1 = (uint32_t)(a_r1 * LDT + a_c) * 2;
        const uint32_t db = (uint32_t)(b_r  * LDT + a_c) * 2;
        cp16(st + OFF_AHI * 2 + d0, Ahi + ga0);
        cp16(st + OFF_AHI * 2 + d1, Ahi + ga1);
        cp16(st + OFF_ALO * 2 + d0, Alo + ga0);
        cp16(st + OFF_ALO * 2 + d1, Alo + ga1);
        cp16(st + OFF_BHI * 2 + db, Bhi + gb);
        cp16(st + OFF_BLO * 2 + db, Blo + gb);
    };

    const int a_row = wm + (lane & 7) + ((lane >> 3) & 1) * 8;
    const int a_col = (lane >> 4) * 8;
    const int b_row = wn + (lane >> 4) * 8 + (lane & 7);
    const int b_col = ((lane >> 3) & 1) * 8;
    const uint32_t aoff = (uint32_t)(a_row * LDT + a_col) * 2;
    const uint32_t boff = (uint32_t)(b_row * LDT + b_col) * 2;

    float acc[4][2][4] = {};

    #pragma unroll
    for (int s = 0; s < STAGES - 1; s++) { load_chunk(s * BK, s); CP_COMMIT(); }

    for (int c = 0; c < CH; c++) {
        CP_WAIT(STAGES - 2);
        __syncthreads();
        const int pc = c + STAGES - 1;
        if (pc < CH) load_chunk(pc * BK, pc % STAGES);
        CP_COMMIT();

        const uint32_t st = sb + (uint32_t)((c % STAGES) * BF3_STG) * 2;
        #pragma unroll
        for (int kk = 0; kk < BK; kk += 16) {
            uint32_t ah[4][4], al[4][4], bh[4], bl[4];
            #pragma unroll
            for (int i = 0; i < 4; i++) {
                ldsm_x4(ah[i], st + OFF_AHI * 2 + aoff + (uint32_t)(i * 16 * LDT + kk) * 2);
                ldsm_x4(al[i], st + OFF_ALO * 2 + aoff + (uint32_t)(i * 16 * LDT + kk) * 2);
            }
            ldsm_x4(bh, st + OFF_BHI * 2 + boff + (uint32_t)kk * 2);
            ldsm_x4(bl, st + OFF_BLO * 2 + boff + (uint32_t)kk * 2);
            #pragma unroll
            for (int i = 0; i < 4; i++)
                #pragma unroll
                for (int j = 0; j < 2; j++) {
                    mma_bf16(acc[i][j], ah[i], &bh[j * 2]);
                    mma_bf16(acc[i][j], ah[i], &bl[j * 2]);
                    mma_bf16(acc[i][j], al[i], &bh[j * 2]);
                }
        }
    }

    const int crow = lane >> 2, ccol = (lane & 3) * 2;
    #pragma unroll
    for (int i = 0; i < 4; i++)
        #pragma unroll
        for (int j = 0; j < 2; j++)
            #pragma unroll
            for (int half = 0; half < 2; half++) {
                const int m = bm + wm + i * 16 + crow + half * 8;
                const int n = bn + wn + j * 8 + ccol;
                __half2 hp = { __float2half_rn(acc[i][j][half * 2 + 0]),
                               __float2half_rn(acc[i][j][half * 2 + 1]) };
                *reinterpret_cast<__half2*>(&Cout[(size_t)m * N + n]) = hp;
            }
}

// ---------------------------------------------------------------------------
// fp16 GEMM, NB = number of B planes (1 or 2)
// ---------------------------------------------------------------------------
template <int NB, bool SCATTER>
__global__ __launch_bounds__(256)
void mma_gemm_h(const __half* __restrict__ A,
                const __half* __restrict__ Bhi,
                const __half* __restrict__ Blo,
                const float* __restrict__ bias,
                float* __restrict__ Cf,
                int M, int N, int K) {
    constexpr int STG = A_ELE + NB * B_ELE;
    extern __shared__ __align__(16) __half hsmem[];
    const uint32_t sb = (uint32_t)__cvta_generic_to_shared(hsmem);
    const int tid = threadIdx.x, lane = tid & 31, wid = tid >> 5;
    const int bm = blockIdx.y * BM, bn = blockIdx.x * BN;
    const int wm = (wid >> 2) * 64, wn = (wid & 3) * 16;
    const int CH = K / BK;

    const int a_r0 = tid >> 2, a_c = (tid & 3) * 8;
    const int a_r1 = (tid + 256) >> 2;
    const int b_r = tid >> 2;

    auto load_chunk = [&](int k0, int s) {
        const uint32_t st = sb + (uint32_t)(s * STG) * 2;
        const size_t ga0 = (size_t)(bm + a_r0) * K + k0 + a_c;
        const size_t ga1 = (size_t)(bm + a_r1) * K + k0 + a_c;
        const size_t gb  = (size_t)(bn + b_r ) * K + k0 + a_c;
        const uint32_t d0 = (uint32_t)(a_r0 * LDT + a_c) * 2;
        const uint32_t d1 = (uint32_t)(a_r1 * LDT + a_c) * 2;
        const uint32_t db = (uint32_t)(b_r  * LDT + a_c) * 2;
        cp16(st + d0, A + ga0);
        cp16(st + d1, A + ga1);
        cp16(st + (uint32_t)A_ELE * 2 + db, Bhi + gb);
        if (NB == 2)
            cp16(st + (uint32_t)(A_ELE + B_ELE) * 2 + db, Blo + gb);
    };

    const int a_row = wm + (lane & 7) + ((lane >> 3) & 1) * 8;
    const int a_col = (lane >> 4) * 8;
    const int b_row = wn + (lane >> 4) * 8 + (lane & 7);
    const int b_col = ((lane >> 3) & 1) * 8;
    const uint32_t aoff = (uint32_t)(a_row * LDT + a_col) * 2;
    const uint32_t boff = (uint32_t)(b_row * LDT + b_col) * 2;

    float acc[4][2][4] = {};

    #pragma unroll
    for (int s = 0; s < STAGES - 1; s++) { load_chunk(s * BK, s); CP_COMMIT(); }

    for (int c = 0; c < CH; c++) {
        CP_WAIT(STAGES - 2);
        __syncthreads();
        const int pc = c + STAGES - 1;
        if (pc < CH) load_chunk(pc * BK, pc % STAGES);
        CP_COMMIT();

        const uint32_t st = sb + (uint32_t)((c % STAGES) * STG) * 2;
        #pragma unroll
        for (int kk = 0; kk < BK; kk += 16) {
            uint32_t a4[4][4], bh[4], bl[4];
            #pragma unroll
            for (int i = 0; i < 4; i++)
                ldsm_x4(a4[i], st + aoff + (uint32_t)(i * 16 * LDT + kk) * 2);
            ldsm_x4(bh, st + (uint32_t)A_ELE * 2 + boff + (uint32_t)kk * 2);
            if (NB == 2)
                ldsm_x4(bl, st + (uint32_t)(A_ELE + B_ELE) * 2 + boff + (uint32_t)kk * 2);
            #pragma unroll
            for (int i = 0; i < 4; i++)
                #pragma unroll
                for (int j = 0; j < 2; j++) {
                    mma_f16(acc[i][j], a4[i], &bh[j * 2]);
                    if (NB == 2) mma_f16(acc[i][j], a4[i], &bl[j * 2]);
                }
        }
    }

    const int crow = lane >> 2, ccol = (lane & 3) * 2;
    #pragma unroll
    for (int i = 0; i < 4; i++)
        #pragma unroll
        for (int j = 0; j < 2; j++)
            #pragma unroll
            for (int half = 0; half < 2; half++) {
                const int m = bm + wm + i * 16 + crow + half * 8;
                const int n = bn + wn + j * 8 + ccol;
                size_t om = (size_t)m;
                if (SCATTER) om = (size_t)(m % TT) * BB + (size_t)(m / TT);
                float2 r = { acc[i][j][half * 2 + 0] + bias[n],
                             acc[i][j][half * 2 + 1] + bias[n + 1] };
                *reinterpret_cast<float2*>(&Cf[om * N + n]) = r;
            }
}

// ---------------------------------------------------------------------------
// persistent RNN recurrence: W_hh single fp16, SMEM-RESIDENT for all 32 steps.
// 8x8-tiled smem layout (each ldmatrix matrix = contiguous 128B, conflict-free).
// CTA tile 128x64, warps 4(m) x 2(n), warp tile 32x32. Grid = 16 x 8 = 128 CTAs.
// smem: W 131072 B + 3 A-stages x 8192 B = 155648 B.
// ---------------------------------------------------------------------------
constexpr unsigned NCTAS = (HH / BN) * (BB / BM);   // 128
constexpr int RNN_W_BYTES = BN * HH * 2;            // 131072
constexpr int RNN_A_STAGE = BM * BK * 2;            // 8192
constexpr int RNN_SMEM = RNN_W_BYTES + STAGES * RNN_A_STAGE;  // 155648

__device__ __forceinline__ void grid_barrier(unsigned target) {
    __syncthreads();
    if (threadIdx.x == 0) {
        __threadfence();
        unsigned arrived = atomicAdd(&g_bar[0], 1u);
        if (arrived == NCTAS - 1) {
            atomicExch(&g_bar[0], 0u);
            __threadfence();
            atomicAdd(&g_bar[1], 1u);
        } else {
            unsigned g;
            do {
                asm volatile("ld.acquire.gpu.u32 %0, [%1];"
                             : "=r"(g) : "l"(g_bar + 1) : "memory");
            } while (g < target);
        }
        __threadfence();
    }
    __syncthreads();
}

__global__ __launch_bounds__(256)
void rnn_persist(const __half* __restrict__ Whh,
                 const float* __restrict__ b_hh,
                 const float* __restrict__ xproj) {
    extern __shared__ __align__(16) __half hsm[];
    const uint32_t WB = (uint32_t)__cvta_generic_to_shared(hsm);
    const uint32_t AB = WB + (uint32_t)RNN_W_BYTES;
    const int tid = threadIdx.x, lane = tid & 31, wid = tid >> 5;
    const int bm = blockIdx.y * BM, bn = blockIdx.x * BN;
    const int warp_m = wid >> 1, warp_n = wid & 1;   // 4 x 2
    const int wm = warp_m * 32, wn = warp_n * 32;
    constexpr int CH = HH / BK;                       // 32

    // ---- one-time: load W tile [BN x HH] into 8x8-tiled smem ----
    // 16B piece (n, kb): n in [0,BN)=row, kb in [0,HH/8)=k-block.
    // dst matrix (nb=n>>3, kb) at WB + (nb*(HH/8) + kb)*128, row (n&7)*16.
    // TOTAL pieces = BN * (HH/8) = 8192   (R7 bug: had (BN/8)*(HH/8)=1024)
    for (int q = tid; q < BN * (HH / 8); q += 256) {
        const int n = q >> 7;          // [0, 64)
        const int kb = q & 127;        // [0, 128)
        const uint32_t dst = WB + (uint32_t)((((n >> 3) * 128 + kb) * 128) + (n & 7) * 16);
        cp16(dst, Whh + (size_t)(bn + n) * HH + kb * 8);
    }
    CP_COMMIT();

    // A-stage loader: 512 pieces of 16B -> 2 per thread
    auto load_A = [&](const __half* h, int k0, int s) {
        #pragma unroll
        for (int i = 0; i < 2; i++) {
            const int p = tid + i * 256;
            const int row = p >> 2, kb = p & 3;
            const uint32_t dst = AB + (uint32_t)(s * RNN_A_STAGE)
                + (uint32_t)(((((row >> 3) << 2) + kb) * 128) + (row & 7) * 16);
            cp16(dst, h + (size_t)(bm + row) * HH + k0 + kb * 8);
        }
    };

    // per-lane ldmatrix offsets
    const int g = lane >> 3, lr = lane & 7;
    const uint32_t aoff_lane = (uint32_t)((g & 1) * 512 + (g >> 1) * 128 + lr * 16);
    const uint32_t boff_lane = (uint32_t)((g >> 1) * 16384 + (g & 1) * 128 + lr * 16);
    const uint32_t a_mb_base = (uint32_t)(warp_m * 4) * 512;
    const uint32_t b_nb_base = (uint32_t)(warp_n * 4) * 16384;

    const int crow = lane >> 2, ccol = (lane & 3) * 2;

    // wait for W before first use
    CP_WAIT(0);
    __syncthreads();

    for (int t = 0; t < TT; t++) {
        const int cur = t & 1;
        const __half* Acur = g_h[cur];
        __half* Nxt = g_h[cur ^ 1];
        const float* xrow = xproj + (size_t)t * BB * HH;

        float acc[2][4][4] = {};

        #pragma unroll
        for (int s = 0; s < STAGES - 1; s++) { load_A(Acur, s * BK, s); CP_COMMIT(); }

        for (int c = 0; c < CH; c++) {
            CP_WAIT(STAGES - 2);
            __syncthreads();
            const int pc = c + STAGES - 1;
            if (pc < CH) load_A(Acur, pc * BK, pc % STAGES);
            CP_COMMIT();

            const uint32_t stA = AB + (uint32_t)((c % STAGES) * RNN_A_STAGE);
            const uint32_t kbW = (uint32_t)(c * 4) * 128;
            #pragma unroll
            for (int kk = 0; kk < 2; kk++) {
                uint32_t a4[2][4], b4[2][4];
                #pragma unroll
                for (int i = 0; i < 2; i++)
                    ldsm_x4(a4[i], stA + a_mb_base + (uint32_t)(i * 2) * 512
                                   + (uint32_t)(kk * 2) * 128 + aoff_lane);
                #pragma unroll
                for (int u = 0; u < 2; u++)
                    ldsm_x4(b4[u], WB + b_nb_base + (uint32_t)(u * 2) * 16384
                                   + kbW + (uint32_t)(kk * 2) * 128 + boff_lane);
                #pragma unroll
                for (int i = 0; i < 2; i++)
                    #pragma unroll
                    for (int j = 0; j < 4; j++)
                        mma_f16(acc[i][j], a4[i], &b4[j >> 1][(j & 1) * 2]);
            }
        }

        // epilogue: h_next = tanh(acc + b_hh + xproj[t]) -> single fp16
        #pragma unroll
        for (int i = 0; i < 2; i++)
            #pragma unroll
            for (int j = 0; j < 4; j++)
                #pragma unroll
                for (int half = 0; half < 2; half++) {
                    const int m = bm + wm + i * 16 + crow + half * 8;
                    const int n = bn + wn + j * 8 + ccol;
                    const float* ar = xrow + (size_t)m * HH;
                    float v0 = tanhf(acc[i][j][half * 2 + 0] + b_hh[n]     + ar[n]);
                    float v1 = tanhf(acc[i][j][half * 2 + 1] + b_hh[n + 1] + ar[n + 1]);
                    __half2 hp = { __float2half_rn(v0), __float2half_rn(v1) };
                    *reinterpret_cast<__half2*>(&Nxt[(size_t)m * HH + n]) = hp;
                }

        if (t + 1 < TT) grid_barrier((unsigned)(t + 1));
    }
}

// ---------------------------------------------------------------------------
// prep kernels
// ---------------------------------------------------------------------------
__global__ void bfused_kernel(const float* __restrict__ W_ih,
                              const float* __restrict__ b_emb,
                              const float* __restrict__ b_ih,
                              float* __restrict__ out) {
    int h = blockIdx.x * blockDim.x + threadIdx.x;
    if (h >= HH) return;
    float s = b_ih[h];
    const float* row = W_ih + (size_t)h * EE;
    #pragma unroll 4
    for (int e = 0; e < EE; e++) s += row[e] * b_emb[e];
    out[h] = s;
}

__global__ void split_bf16_kernel(const float* __restrict__ in,
                                  __nv_bfloat16* __restrict__ hi,
                                  __nv_bfloat16* __restrict__ lo,
                                  int n4) {
    int idx = blockIdx.x * blockDim.x + threadIdx.x;
    for (; idx < n4; idx += gridDim.x * blockDim.x) {
        float4 v = reinterpret_cast<const float4*>(in)[idx];
        __nv_bfloat162 hp0, hp1, lp0, lp1;
        bf16_split(v.x, hp0.x, lp0.x);
        bf16_split(v.y, hp0.y, lp0.y);
        bf16_split(v.z, hp1.x, lp1.x);
        bf16_split(v.w, hp1.y, lp1.y);
        reinterpret_cast<__nv_bfloat162*>(hi)[idx * 2 + 0] = hp0;
        reinterpret_cast<__nv_bfloat162*>(hi)[idx * 2 + 1] = hp1;
        reinterpret_cast<__nv_bfloat162*>(lo)[idx * 2 + 0] = lp0;
        reinterpret_cast<__nv_bfloat162*>(lo)[idx * 2 + 1] = lp1;
    }
}

__global__ void split_f16_kernel(const float* __restrict__ in,
                                 __half* __restrict__ hi,
                                 __half* __restrict__ lo,
                                 int n4) {
    int idx = blockIdx.x * blockDim.x + threadIdx.x;
    for (; idx < n4; idx += gridDim.x * blockDim.x) {
        float4 v = reinterpret_cast<const float4*>(in)[idx];
        __half2 hp0, hp1, lp0, lp1;
        f16_split(v.x, hp0.x, lp0.x);
        f16_split(v.y, hp0.y, lp0.y);
        f16_split(v.z, hp1.x, lp1.x);
        f16_split(v.w, hp1.y, lp1.y);
        reinterpret_cast<__half2*>(hi)[idx * 2 + 0] = hp0;
        reinterpret_cast<__half2*>(hi)[idx * 2 + 1] = hp1;
        reinterpret_cast<__half2*>(lo)[idx * 2 + 0] = lp0;
        reinterpret_cast<__half2*>(lo)[idx * 2 + 1] = lp1;
    }
}

__global__ void cvt_f16_kernel(const float* __restrict__ in,
                               __half* __restrict__ out, int n4) {
    int idx = blockIdx.x * blockDim.x + threadIdx.x;
    for (; idx < n4; idx += gridDim.x * blockDim.x) {
        float4 v = reinterpret_cast<const float4*>(in)[idx];
        __half2 p0 = { __float2half_rn(v.x), __float2half_rn(v.y) };
        __half2 p1 = { __float2half_rn(v.z), __float2half_rn(v.w) };
        reinterpret_cast<__half2*>(out)[idx * 2 + 0] = p0;
        reinterpret_cast<__half2*>(out)[idx * 2 + 1] = p1;
    }
}

__global__ void transpose_split_kernel(const float* __restrict__ in,
                                       __nv_bfloat16* __restrict__ hi,
                                       __nv_bfloat16* __restrict__ lo) {
    __shared__ float t[32][33];
    const int v0 = blockIdx.x * 32, e0 = blockIdx.y * 32;
    for (int i = threadIdx.y; i < 32; i += 8)
        t[i][threadIdx.x] = in[(size_t)(e0 + i) * VV + v0 + threadIdx.x];
    __syncthreads();
    for (int i = threadIdx.y; i < 32; i += 8) {
        float x = t[threadIdx.x][i];
        __nv_bfloat16 h, l;
        bf16_split(x, h, l);
        size_t o = (size_t)(v0 + i) * EE + e0 + threadIdx.x;
        hi[o] = h;
        lo[o] = l;
    }
}

// ---------------------------------------------------------------------------
extern "C" void kernel_launch(void* const* d_in, const int* in_sizes, int n_in,
                              void* d_out, int out_size) {
    const float* msg   = (const float*)d_in[0];
    const float* W_emb = (const float*)d_in[1];
    const float* b_emb = (const float*)d_in[2];
    const float* W_ih  = (const float*)d_in[3];
    const float* b_ih  = (const float*)d_in[4];
    const float* W_hh  = (const float*)d_in[5];
    const float* b_hh  = (const float*)d_in[6];
    const float* W_out = (const float*)d_in[7];
    const float* b_out = (const float*)d_in[8];
    float* out = (float*)d_out;

    float *bfused, *xproj;
    __half *msg_h, *wf, *whh, *wout_hi, *wout_lo, *hbuf;
    __nv_bfloat16 *wembT_hi, *wembT_lo, *wih_hi, *wih_lo;
    unsigned* bar;
    cudaGetSymbolAddress((void**)&bfused,   g_bfused);
    cudaGetSymbolAddress((void**)&xproj,    g_xproj);
    cudaGetSymbolAddress((void**)&msg_h,    g_msg_h);
    cudaGetSymbolAddress((void**)&wembT_hi, g_wembT_hi);
    cudaGetSymbolAddress((void**)&wembT_lo, g_wembT_lo);
    cudaGetSymbolAddress((void**)&wih_hi,   g_wih_hi);
    cudaGetSymbolAddress((void**)&wih_lo,   g_wih_lo);
    cudaGetSymbolAddress((void**)&wf,       g_wf);
    cudaGetSymbolAddress((void**)&whh,      g_whh);
    cudaGetSymbolAddress((void**)&wout_hi,  g_wout_hi);
    cudaGetSymbolAddress((void**)&wout_lo,  g_wout_lo);
    cudaGetSymbolAddress((void**)&hbuf,     g_h);
    cudaGetSymbolAddress((void**)&bar,      g_bar);

    cudaFuncSetAttribute(mma_gemm_bf3, cudaFuncAttributeMaxDynamicSharedMemorySize, BF3_SMEM);
    cudaFuncSetAttribute(mma_gemm_h<1, true>,
                         cudaFuncAttributeMaxDynamicSharedMemorySize,
                         STAGES * (A_ELE + B_ELE) * 2);
    cudaFuncSetAttribute(mma_gemm_h<2, false>,
                         cudaFuncAttributeMaxDynamicSharedMemorySize,
                         STAGES * (A_ELE + 2 * B_ELE) * 2);
    cudaFuncSetAttribute(rnn_persist, cudaFuncAttributeMaxDynamicSharedMemorySize, RNN_SMEM);

    cudaMemsetAsync(hbuf, 0, (size_t)BB * HH * sizeof(__half), 0);
    cudaMemsetAsync(bar, 0, 2 * sizeof(unsigned), 0);

    bfused_kernel<<<(HH + 255) / 256, 256>>>(W_ih, b_emb, b_ih, bfused);

    transpose_split_kernel<<<dim3(VV / 32, EE / 32), dim3(32, 8)>>>(W_emb, wembT_hi, wembT_lo);
    split_bf16_kernel<<<512, 256>>>(W_ih, wih_hi, wih_lo, HH * EE / 4);
    cvt_f16_kernel<<<2048, 256>>>(W_hh, whh, HH * HH / 4);
    split_f16_kernel<<<2048, 256>>>(W_out, wout_hi, wout_lo, OO * HH / 4);
    cvt_f16_kernel<<<8192, 256>>>(msg, msg_h, BB * TT * VV / 4);

    // W_fused = W_ih @ W_emb  (bf16 3-term, single fp16 output)
    mma_gemm_bf3<<<dim3(VV / BN, HH / BM), 256, BF3_SMEM>>>(
        wih_hi, wih_lo, wembT_hi, wembT_lo, wf, HH, VV, EE);

    // x_proj = msg @ W_fused^T + b_fused  (fp16 1-term, scatter [B*T]->[T,B])
    mma_gemm_h<1, true><<<dim3(HH / BN, (BB * TT) / BM), 256,
                          STAGES * (A_ELE + B_ELE) * 2>>>(
        msg_h, wf, nullptr, bfused, xproj, BB * TT, HH, VV);

    // recurrence: 32 steps, persistent, W_hh smem-resident (final h -> buffer 0)
    rnn_persist<<<dim3(HH / BN, BB / BM), 256, RNN_SMEM>>>(whh, b_hh, xproj);

    // out = h_T @ W_out^T + b_out  (fp16 2-term)
    mma_gemm_h<2, false><<<dim3(OO / BN, BB / BM), 256,
                           STAGES * (A_ELE + 2 * B_ELE) * 2>>>(
        hbuf, wout_hi, wout_lo, b_out, out, BB, OO, HH);
}